// round 1
// baseline (speedup 1.0000x reference)
#include <cuda_runtime.h>
#include <math.h>

// Problem constants (fixed by the dataset)
#define T_TOK 2048
#define H_DIM 2048
#define E_NUM 8
#define I_DIM 5632
#define TOPK  2
#define R_NUM (T_TOK * TOPK)   // 4096 (token, slot) assignments

// GEMM tiling
#define BM 128
#define BN 64
#define BK 16

// ---------------- device scratch (static; no runtime allocation) ----------------
__device__ float g_h[(size_t)R_NUM * I_DIM];   // silu(g)*u, sorted-row order (~92 MB)
__device__ int   g_row_token[R_NUM];
__device__ float g_row_gate[R_NUM];
__device__ int   g_counts[E_NUM];
__device__ int   g_offsets[E_NUM];
__device__ int   g_fill[E_NUM];
__device__ int   g_tok_exp[R_NUM];
__device__ float g_tok_gate[R_NUM];

// ---------------- routing ----------------
__global__ void k_zero() {
    int i = threadIdx.x;
    if (i < E_NUM) { g_counts[i] = 0; g_fill[i] = 0; }
}

__global__ void k_route(const float* __restrict__ logits) {
    int t = blockIdx.x * blockDim.x + threadIdx.x;
    if (t >= T_TOK) return;
    float v[E_NUM];
    float mx = -1e30f;
#pragma unroll
    for (int e = 0; e < E_NUM; e++) { v[e] = logits[t * E_NUM + e]; mx = fmaxf(mx, v[e]); }
#pragma unroll
    for (int e = 0; e < E_NUM; e++) v[e] = __expf(v[e] - mx);
    // top-2 over exps (same order as softmax probs)
    int e1 = 0;
#pragma unroll
    for (int e = 1; e < E_NUM; e++) if (v[e] > v[e1]) e1 = e;
    int e2 = (e1 == 0) ? 1 : 0;
#pragma unroll
    for (int e = 0; e < E_NUM; e++) if (e != e1 && v[e] > v[e2]) e2 = e;
    float p1 = v[e1], p2 = v[e2];
    float inv = 1.0f / (p1 + p2);     // softmax denominators cancel in the ratio
    g_tok_exp[2 * t] = e1;  g_tok_exp[2 * t + 1] = e2;
    g_tok_gate[2 * t] = p1 * inv; g_tok_gate[2 * t + 1] = p2 * inv;
    atomicAdd(&g_counts[e1], 1);
    atomicAdd(&g_counts[e2], 1);
}

__global__ void k_prefix() {
    int acc = 0;
    for (int e = 0; e < E_NUM; e++) { g_offsets[e] = acc; acc += g_counts[e]; }
}

__global__ void k_scatter() {
    int t = blockIdx.x * blockDim.x + threadIdx.x;
    if (t >= T_TOK) return;
#pragma unroll
    for (int s = 0; s < TOPK; s++) {
        int e = g_tok_exp[2 * t + s];
        int pos = g_offsets[e] + atomicAdd(&g_fill[e], 1);
        g_row_token[pos] = t;
        g_row_gate[pos] = g_tok_gate[2 * t + s];
    }
}

// ---------------- GEMM1: h = silu(x @ Wg^T) * (x @ Wu^T), per expert ----------------
__global__ __launch_bounds__(256) void k_gemm1(const float* __restrict__ x,
                                               const float* __restrict__ w13) {
    const int e = blockIdx.z;
    const int cnt = g_counts[e];
    const int rowt = blockIdx.y * BM;
    if (rowt >= cnt) return;
    const int base = g_offsets[e];
    const int i0 = blockIdx.x * BN;

    __shared__ float As[BK][BM + 4];
    __shared__ float Bg[BK][BN + 4];
    __shared__ float Bu[BK][BN + 4];

    const int tid = threadIdx.x;
    const int arow = tid >> 2;        // 0..63
    const int acol = (tid & 3) * 4;   // 0,4,8,12

    const bool v0 = (rowt + arow) < cnt;
    const bool v1 = (rowt + arow + 64) < cnt;
    const int tok0 = v0 ? g_row_token[base + rowt + arow] : 0;
    const int tok1 = v1 ? g_row_token[base + rowt + arow + 64] : 0;
    const float* pa0 = x + (size_t)tok0 * H_DIM + acol;
    const float* pa1 = x + (size_t)tok1 * H_DIM + acol;

    const float* pg = w13 + (size_t)e * (2 * I_DIM) * H_DIM
                          + (size_t)(i0 + arow) * H_DIM + acol;
    const float* pu = pg + (size_t)I_DIM * H_DIM;

    const int ty = tid >> 4;   // 0..15 : row group
    const int tx = tid & 15;   // 0..15 : col group

    float accg[8][4], accu[8][4];
#pragma unroll
    for (int j = 0; j < 8; j++)
#pragma unroll
        for (int c = 0; c < 4; c++) { accg[j][c] = 0.f; accu[j][c] = 0.f; }

    for (int k0 = 0; k0 < H_DIM; k0 += BK) {
        float4 a0 = v0 ? *(const float4*)(pa0 + k0) : make_float4(0, 0, 0, 0);
        float4 a1 = v1 ? *(const float4*)(pa1 + k0) : make_float4(0, 0, 0, 0);
        float4 bg = *(const float4*)(pg + k0);
        float4 bu = *(const float4*)(pu + k0);
        As[acol + 0][arow] = a0.x; As[acol + 1][arow] = a0.y;
        As[acol + 2][arow] = a0.z; As[acol + 3][arow] = a0.w;
        As[acol + 0][arow + 64] = a1.x; As[acol + 1][arow + 64] = a1.y;
        As[acol + 2][arow + 64] = a1.z; As[acol + 3][arow + 64] = a1.w;
        Bg[acol + 0][arow] = bg.x; Bg[acol + 1][arow] = bg.y;
        Bg[acol + 2][arow] = bg.z; Bg[acol + 3][arow] = bg.w;
        Bu[acol + 0][arow] = bu.x; Bu[acol + 1][arow] = bu.y;
        Bu[acol + 2][arow] = bu.z; Bu[acol + 3][arow] = bu.w;
        __syncthreads();
#pragma unroll
        for (int kk = 0; kk < BK; kk++) {
            float a[8], bgv[4], buv[4];
            *(float4*)&a[0] = *(const float4*)&As[kk][ty * 8];
            *(float4*)&a[4] = *(const float4*)&As[kk][ty * 8 + 4];
            *(float4*)&bgv[0] = *(const float4*)&Bg[kk][tx * 4];
            *(float4*)&buv[0] = *(const float4*)&Bu[kk][tx * 4];
#pragma unroll
            for (int j = 0; j < 8; j++)
#pragma unroll
                for (int c = 0; c < 4; c++) {
                    accg[j][c] += a[j] * bgv[c];
                    accu[j][c] += a[j] * buv[c];
                }
        }
        __syncthreads();
    }

#pragma unroll
    for (int j = 0; j < 8; j++) {
        int lr = ty * 8 + j;
        if (rowt + lr < cnt) {
            float hv[4];
#pragma unroll
            for (int c = 0; c < 4; c++) {
                float g = accg[j][c];
                float s = g / (1.0f + __expf(-g));   // silu
                hv[c] = s * accu[j][c];
            }
            *(float4*)&g_h[(size_t)(base + rowt + lr) * I_DIM + i0 + tx * 4] =
                *(float4*)&hv[0];
        }
    }
}

// ---------------- GEMM2: out[token] += gate * (h @ w2[e]^T) ----------------
__global__ __launch_bounds__(256) void k_gemm2(const float* __restrict__ w2,
                                               float* __restrict__ out) {
    const int e = blockIdx.z;
    const int cnt = g_counts[e];
    const int rowt = blockIdx.y * BM;
    if (rowt >= cnt) return;
    const int base = g_offsets[e];
    const int n0 = blockIdx.x * BN;

    __shared__ float As[BK][BM + 4];
    __shared__ float Bs[BK][BN + 4];

    const int tid = threadIdx.x;
    const int arow = tid >> 2;
    const int acol = (tid & 3) * 4;

    // clamp invalid rows into range (epilogue guards correctness)
    const int ar0 = min(rowt + arow, cnt - 1);
    const int ar1 = min(rowt + arow + 64, cnt - 1);
    const float* pa0 = g_h + (size_t)(base + ar0) * I_DIM + acol;
    const float* pa1 = g_h + (size_t)(base + ar1) * I_DIM + acol;

    const float* pb = w2 + (size_t)e * H_DIM * I_DIM
                         + (size_t)(n0 + arow) * I_DIM + acol;

    const int ty = tid >> 4;
    const int tx = tid & 15;

    float acc[8][4];
#pragma unroll
    for (int j = 0; j < 8; j++)
#pragma unroll
        for (int c = 0; c < 4; c++) acc[j][c] = 0.f;

    for (int k0 = 0; k0 < I_DIM; k0 += BK) {
        float4 a0 = *(const float4*)(pa0 + k0);
        float4 a1 = *(const float4*)(pa1 + k0);
        float4 b = *(const float4*)(pb + k0);
        As[acol + 0][arow] = a0.x; As[acol + 1][arow] = a0.y;
        As[acol + 2][arow] = a0.z; As[acol + 3][arow] = a0.w;
        As[acol + 0][arow + 64] = a1.x; As[acol + 1][arow + 64] = a1.y;
        As[acol + 2][arow + 64] = a1.z; As[acol + 3][arow + 64] = a1.w;
        Bs[acol + 0][arow] = b.x; Bs[acol + 1][arow] = b.y;
        Bs[acol + 2][arow] = b.z; Bs[acol + 3][arow] = b.w;
        __syncthreads();
#pragma unroll
        for (int kk = 0; kk < BK; kk++) {
            float a[8], bv[4];
            *(float4*)&a[0] = *(const float4*)&As[kk][ty * 8];
            *(float4*)&a[4] = *(const float4*)&As[kk][ty * 8 + 4];
            *(float4*)&bv[0] = *(const float4*)&Bs[kk][tx * 4];
#pragma unroll
            for (int j = 0; j < 8; j++)
#pragma unroll
                for (int c = 0; c < 4; c++)
                    acc[j][c] += a[j] * bv[c];
        }
        __syncthreads();
    }

#pragma unroll
    for (int j = 0; j < 8; j++) {
        int lr = ty * 8 + j;
        int row = rowt + lr;
        if (row < cnt) {
            int token = g_row_token[base + row];
            float gate = g_row_gate[base + row];
            float* po = out + (size_t)token * H_DIM + n0 + tx * 4;
#pragma unroll
            for (int c = 0; c < 4; c++)
                atomicAdd(po + c, gate * acc[j][c]);
        }
    }
}

// ---------------- launch ----------------
extern "C" void kernel_launch(void* const* d_in, const int* in_sizes, int n_in,
                              void* d_out, int out_size) {
    const float* x      = (const float*)d_in[0];  // [T, H]
    const float* logits = (const float*)d_in[1];  // [T, E]
    const float* w13    = (const float*)d_in[2];  // [E, 2I, H]
    const float* w2     = (const float*)d_in[3];  // [E, H, I]
    float* out = (float*)d_out;                   // [T, H]
    (void)in_sizes; (void)n_in;

    cudaMemsetAsync(out, 0, (size_t)out_size * sizeof(float));
    k_zero<<<1, 32>>>();
    k_route<<<T_TOK / 256, 256>>>(logits);
    k_prefix<<<1, 1>>>();
    k_scatter<<<T_TOK / 256, 256>>>();

    dim3 g1(I_DIM / BN, T_TOK / BM, E_NUM);   // 88 x 16 x 8
    k_gemm1<<<g1, 256>>>(x, w13);
    dim3 g2(H_DIM / BN, T_TOK / BM, E_NUM);   // 32 x 16 x 8
    k_gemm2<<<g2, 256>>>(w2, out);
}

// round 2
// speedup vs baseline: 1.3663x; 1.3663x over previous
#include <cuda_runtime.h>
#include <math.h>
#include <stdint.h>

// Problem constants
#define T_TOK 2048
#define H_DIM 2048
#define E_NUM 8
#define I_DIM 5632
#define N2I   (2 * I_DIM)      // 11264
#define TOPK  2
#define R_NUM (T_TOK * TOPK)   // 4096

// Tiling
#define BM 128
#define BN 128
#define BK 16
#define AS_STRIDE 132          // floats per k-row in smem (128 + 4 pad)

// ---------------- device scratch ----------------
__device__ float g_gu[(size_t)R_NUM * N2I];    // x @ w13^T   (~184 MB)
__device__ float g_h[(size_t)R_NUM * I_DIM];   // silu(g)*u   (~92 MB)
__device__ int   g_row_token[R_NUM];
__device__ float g_row_gate[R_NUM];
__device__ int   g_counts[E_NUM];
__device__ int   g_offsets[E_NUM];
__device__ int   g_fill[E_NUM];
__device__ int   g_tok_exp[R_NUM];
__device__ float g_tok_gate[R_NUM];

// ---------------- routing ----------------
__global__ void k_zero() {
    int i = threadIdx.x;
    if (i < E_NUM) { g_counts[i] = 0; g_fill[i] = 0; }
}

__global__ void k_route(const float* __restrict__ logits) {
    int t = blockIdx.x * blockDim.x + threadIdx.x;
    if (t >= T_TOK) return;
    float v[E_NUM];
    float mx = -1e30f;
#pragma unroll
    for (int e = 0; e < E_NUM; e++) { v[e] = logits[t * E_NUM + e]; mx = fmaxf(mx, v[e]); }
#pragma unroll
    for (int e = 0; e < E_NUM; e++) v[e] = __expf(v[e] - mx);
    int e1 = 0;
#pragma unroll
    for (int e = 1; e < E_NUM; e++) if (v[e] > v[e1]) e1 = e;
    int e2 = (e1 == 0) ? 1 : 0;
#pragma unroll
    for (int e = 0; e < E_NUM; e++) if (e != e1 && v[e] > v[e2]) e2 = e;
    float p1 = v[e1], p2 = v[e2];
    float inv = 1.0f / (p1 + p2);
    g_tok_exp[2 * t] = e1;  g_tok_exp[2 * t + 1] = e2;
    g_tok_gate[2 * t] = p1 * inv; g_tok_gate[2 * t + 1] = p2 * inv;
    atomicAdd(&g_counts[e1], 1);
    atomicAdd(&g_counts[e2], 1);
}

__global__ void k_prefix() {
    int acc = 0;
    for (int e = 0; e < E_NUM; e++) { g_offsets[e] = acc; acc += g_counts[e]; }
}

__global__ void k_scatter() {
    int t = blockIdx.x * blockDim.x + threadIdx.x;
    if (t >= T_TOK) return;
#pragma unroll
    for (int s = 0; s < TOPK; s++) {
        int e = g_tok_exp[2 * t + s];
        int pos = g_offsets[e] + atomicAdd(&g_fill[e], 1);
        g_row_token[pos] = t;
        g_row_gate[pos] = g_tok_gate[2 * t + s];
    }
}

// ---------------- tf32 helpers ----------------
__device__ __forceinline__ float f2tf(float x) {
    uint32_t u;
    asm("cvt.rna.tf32.f32 %0, %1;" : "=r"(u) : "f"(x));
    return __uint_as_float(u);
}

__device__ __forceinline__ void sts_seg(float* S, int m, int s, float4 v) {
    int b = (m & 7) * 16 + (m >> 3);
    S[(s * 4 + 0) * AS_STRIDE + b] = f2tf(v.x);
    S[(s * 4 + 1) * AS_STRIDE + b] = f2tf(v.y);
    S[(s * 4 + 2) * AS_STRIDE + b] = f2tf(v.z);
    S[(s * 4 + 3) * AS_STRIDE + b] = f2tf(v.w);
}

#define MMA_TF32(ac, aa, bb)                                                     \
    asm volatile(                                                                \
        "mma.sync.aligned.m16n8k8.row.col.f32.tf32.tf32.f32 "                    \
        "{%0,%1,%2,%3},{%4,%5,%6,%7},{%8,%9},{%0,%1,%2,%3};"                     \
        : "+f"(ac[0]), "+f"(ac[1]), "+f"(ac[2]), "+f"(ac[3])                     \
        : "r"(aa[0]), "r"(aa[1]), "r"(aa[2]), "r"(aa[3]), "r"(bb[0]), "r"(bb[1]))

// warp-tile compute over one BK=16 smem stage
__device__ __forceinline__ void compute_stage(const float* SA_, const float* SB_,
                                              int lr, int cg, int wm, int wn,
                                              float acc[4][4][4]) {
#pragma unroll
    for (int kk = 0; kk < 2; kk++) {
        uint32_t a[4][4];
        uint32_t b[4][2];
#pragma unroll
        for (int p = 0; p < 2; p++) {
            const float4* ap = reinterpret_cast<const float4*>(
                SA_ + (kk * 8 + p * 4 + cg) * AS_STRIDE + lr * 16 + wm * 8);
            float4 v0 = ap[0], v1 = ap[1];
            a[0][p * 2 + 0] = __float_as_uint(v0.x);
            a[0][p * 2 + 1] = __float_as_uint(v0.y);
            a[1][p * 2 + 0] = __float_as_uint(v0.z);
            a[1][p * 2 + 1] = __float_as_uint(v0.w);
            a[2][p * 2 + 0] = __float_as_uint(v1.x);
            a[2][p * 2 + 1] = __float_as_uint(v1.y);
            a[3][p * 2 + 0] = __float_as_uint(v1.z);
            a[3][p * 2 + 1] = __float_as_uint(v1.w);
        }
#pragma unroll
        for (int p = 0; p < 2; p++) {
            const float4 w = *reinterpret_cast<const float4*>(
                SB_ + (kk * 8 + p * 4 + cg) * AS_STRIDE + lr * 16 + wn * 4);
            b[0][p] = __float_as_uint(w.x);
            b[1][p] = __float_as_uint(w.y);
            b[2][p] = __float_as_uint(w.z);
            b[3][p] = __float_as_uint(w.w);
        }
#pragma unroll
        for (int mt = 0; mt < 4; mt++)
#pragma unroll
            for (int nt = 0; nt < 4; nt++)
                MMA_TF32(acc[mt][nt], a[mt], b[nt]);
    }
}

// ---------------- GEMM1: gu = x_gathered @ w13^T ----------------
__global__ __launch_bounds__(256, 2) void k_gemm1(const float* __restrict__ x,
                                                  const float* __restrict__ w13) {
    const int e = blockIdx.z;
    const int cnt = g_counts[e];
    const int rowt = blockIdx.x * BM;
    if (rowt >= cnt) return;
    const int base = g_offsets[e];
    const int n0 = blockIdx.y * BN;

    __shared__ float SA[2][BK * AS_STRIDE];
    __shared__ float SB[2][BK * AS_STRIDE];

    const int tid = threadIdx.x;
    const int am = tid & 127;
    const int sq = tid >> 7;          // 0/1 -> segs {sq, sq+2}

    // A row (gathered token)
    const int rowA = rowt + am;
    const bool av = rowA < cnt;
    const float* aptr = x + (size_t)(av ? g_row_token[base + rowA] : 0) * H_DIM;
    // B row (weight, N = 2I)
    const float* bptr = w13 + (size_t)e * N2I * H_DIM + (size_t)(n0 + am) * H_DIM;

    const int lane = tid & 31, wid = tid >> 5;
    const int lr = lane >> 2, cg = lane & 3;
    const int wm = wid >> 2, wn = wid & 3;

    float acc[4][4][4];
#pragma unroll
    for (int mt = 0; mt < 4; mt++)
#pragma unroll
        for (int nt = 0; nt < 4; nt++)
#pragma unroll
            for (int c = 0; c < 4; c++) acc[mt][nt][c] = 0.f;

    const int NK = H_DIM / BK;   // 128
    float4 va0, va1, vb0, vb1;

    // prologue: load + store stage 0
    {
        const float4 z = make_float4(0, 0, 0, 0);
        va0 = av ? *(const float4*)(aptr + sq * 4) : z;
        va1 = av ? *(const float4*)(aptr + (sq + 2) * 4) : z;
        vb0 = *(const float4*)(bptr + sq * 4);
        vb1 = *(const float4*)(bptr + (sq + 2) * 4);
        sts_seg(SA[0], am, sq, va0);  sts_seg(SA[0], am, sq + 2, va1);
        sts_seg(SB[0], am, sq, vb0);  sts_seg(SB[0], am, sq + 2, vb1);
    }
    __syncthreads();

    for (int it = 0; it < NK; it++) {
        if (it + 1 < NK) {
            const int k0 = (it + 1) * BK;
            const float4 z = make_float4(0, 0, 0, 0);
            va0 = av ? *(const float4*)(aptr + k0 + sq * 4) : z;
            va1 = av ? *(const float4*)(aptr + k0 + (sq + 2) * 4) : z;
            vb0 = *(const float4*)(bptr + k0 + sq * 4);
            vb1 = *(const float4*)(bptr + k0 + (sq + 2) * 4);
        }
        compute_stage(SA[it & 1], SB[it & 1], lr, cg, wm, wn, acc);
        __syncthreads();
        if (it + 1 < NK) {
            const int nb = (it + 1) & 1;
            sts_seg(SA[nb], am, sq, va0);  sts_seg(SA[nb], am, sq + 2, va1);
            sts_seg(SB[nb], am, sq, vb0);  sts_seg(SB[nb], am, sq + 2, vb1);
            __syncthreads();
        }
    }

    // epilogue: write gu
#pragma unroll
    for (int mt = 0; mt < 4; mt++) {
        const int r = rowt + wm * 64 + mt * 16 + lr;
#pragma unroll
        for (int nt = 0; nt < 4; nt++) {
            const int col = n0 + wn * 32 + nt * 8 + cg * 2;
            if (r < cnt) {
                float2 v = make_float2(acc[mt][nt][0], acc[mt][nt][1]);
                *(float2*)&g_gu[(size_t)(base + r) * N2I + col] = v;
            }
            if (r + 8 < cnt) {
                float2 v = make_float2(acc[mt][nt][2], acc[mt][nt][3]);
                *(float2*)&g_gu[(size_t)(base + r + 8) * N2I + col] = v;
            }
        }
    }
}

// ---------------- activation: h = silu(g) * u ----------------
__global__ __launch_bounds__(256) void k_act() {
    const int IQ = I_DIM / 4;          // float4s per row half
    size_t idx = (size_t)blockIdx.x * blockDim.x + threadIdx.x;
    if (idx >= (size_t)R_NUM * IQ) return;
    int r = (int)(idx / IQ);
    int q = (int)(idx % IQ);
    const float4* gu4 = (const float4*)&g_gu[(size_t)r * N2I];
    float4 g = gu4[q];
    float4 u = gu4[IQ + q];
    float4 h;
    h.x = (g.x / (1.f + __expf(-g.x))) * u.x;
    h.y = (g.y / (1.f + __expf(-g.y))) * u.y;
    h.z = (g.z / (1.f + __expf(-g.z))) * u.z;
    h.w = (g.w / (1.f + __expf(-g.w))) * u.w;
    *(float4*)&g_h[(size_t)r * I_DIM + q * 4] = h;
}

// ---------------- GEMM2: out[token] += gate * (h @ w2^T) ----------------
__global__ __launch_bounds__(256, 2) void k_gemm2(const float* __restrict__ w2,
                                                  float* __restrict__ out) {
    const int e = blockIdx.z;
    const int cnt = g_counts[e];
    const int rowt = blockIdx.x * BM;
    if (rowt >= cnt) return;
    const int base = g_offsets[e];
    const int n0 = blockIdx.y * BN;

    __shared__ float SA[2][BK * AS_STRIDE];
    __shared__ float SB[2][BK * AS_STRIDE];

    const int tid = threadIdx.x;
    const int am = tid & 127;
    const int sq = tid >> 7;

    const int rowA = min(rowt + am, cnt - 1);   // clamp; epilogue guards
    const float* aptr = g_h + (size_t)(base + rowA) * I_DIM;
    const float* bptr = w2 + (size_t)e * H_DIM * I_DIM + (size_t)(n0 + am) * I_DIM;

    const int lane = tid & 31, wid = tid >> 5;
    const int lr = lane >> 2, cg = lane & 3;
    const int wm = wid >> 2, wn = wid & 3;

    float acc[4][4][4];
#pragma unroll
    for (int mt = 0; mt < 4; mt++)
#pragma unroll
        for (int nt = 0; nt < 4; nt++)
#pragma unroll
            for (int c = 0; c < 4; c++) acc[mt][nt][c] = 0.f;

    const int NK = I_DIM / BK;   // 352
    float4 va0, va1, vb0, vb1;

    {
        va0 = *(const float4*)(aptr + sq * 4);
        va1 = *(const float4*)(aptr + (sq + 2) * 4);
        vb0 = *(const float4*)(bptr + sq * 4);
        vb1 = *(const float4*)(bptr + (sq + 2) * 4);
        sts_seg(SA[0], am, sq, va0);  sts_seg(SA[0], am, sq + 2, va1);
        sts_seg(SB[0], am, sq, vb0);  sts_seg(SB[0], am, sq + 2, vb1);
    }
    __syncthreads();

    for (int it = 0; it < NK; it++) {
        if (it + 1 < NK) {
            const int k0 = (it + 1) * BK;
            va0 = *(const float4*)(aptr + k0 + sq * 4);
            va1 = *(const float4*)(aptr + k0 + (sq + 2) * 4);
            vb0 = *(const float4*)(bptr + k0 + sq * 4);
            vb1 = *(const float4*)(bptr + k0 + (sq + 2) * 4);
        }
        compute_stage(SA[it & 1], SB[it & 1], lr, cg, wm, wn, acc);
        __syncthreads();
        if (it + 1 < NK) {
            const int nb = (it + 1) & 1;
            sts_seg(SA[nb], am, sq, va0);  sts_seg(SA[nb], am, sq + 2, va1);
            sts_seg(SB[nb], am, sq, vb0);  sts_seg(SB[nb], am, sq + 2, vb1);
            __syncthreads();
        }
    }

#pragma unroll
    for (int mt = 0; mt < 4; mt++) {
        const int r0 = rowt + wm * 64 + mt * 16 + lr;
#pragma unroll
        for (int rr = 0; rr < 2; rr++) {
            const int r = r0 + rr * 8;
            if (r < cnt) {
                const int token = g_row_token[base + r];
                const float gate = g_row_gate[base + r];
                float* po = out + (size_t)token * H_DIM;
#pragma unroll
                for (int nt = 0; nt < 4; nt++) {
                    const int col = n0 + wn * 32 + nt * 8 + cg * 2;
                    atomicAdd(po + col,     gate * acc[mt][nt][rr * 2 + 0]);
                    atomicAdd(po + col + 1, gate * acc[mt][nt][rr * 2 + 1]);
                }
            }
        }
    }
}

// ---------------- launch ----------------
extern "C" void kernel_launch(void* const* d_in, const int* in_sizes, int n_in,
                              void* d_out, int out_size) {
    const float* x      = (const float*)d_in[0];  // [T, H]
    const float* logits = (const float*)d_in[1];  // [T, E]
    const float* w13    = (const float*)d_in[2];  // [E, 2I, H]
    const float* w2     = (const float*)d_in[3];  // [E, H, I]
    float* out = (float*)d_out;                   // [T, H]
    (void)in_sizes; (void)n_in;

    cudaMemsetAsync(out, 0, (size_t)out_size * sizeof(float));
    k_zero<<<1, 32>>>();
    k_route<<<T_TOK / 256, 256>>>(logits);
    k_prefix<<<1, 1>>>();
    k_scatter<<<T_TOK / 256, 256>>>();

    // GEMM1: grid (row-blocks, N-tiles, experts) — x fastest so concurrent
    // CTAs share the same B tile through L2.
    dim3 g1(T_TOK * TOPK / BM, N2I / BN, E_NUM);   // 32 x 88 x 8
    k_gemm1<<<g1, 256>>>(x, w13);

    int act_threads = (int)((size_t)R_NUM * (I_DIM / 4));
    k_act<<<(act_threads + 255) / 256, 256>>>();

    dim3 g2(T_TOK * TOPK / BM, H_DIM / BN, E_NUM); // 32 x 16 x 8
    k_gemm2<<<g2, 256>>>(w2, out);
}

// round 4
// speedup vs baseline: 1.3905x; 1.0177x over previous
#include <cuda_runtime.h>
#include <math.h>
#include <stdint.h>

// Problem constants
#define T_TOK 2048
#define H_DIM 2048
#define E_NUM 8
#define I_DIM 5632
#define N2I   (2 * I_DIM)
#define TOPK  2
#define R_NUM (T_TOK * TOPK)

// Tiling
#define BM 128
#define BN 128
#define BK 16
#define AS_STRIDE 132

// ---------------- device scratch ----------------
__device__ float g_h[(size_t)R_NUM * I_DIM];   // silu(g)*u (~92 MB)
__device__ int   g_row_token[R_NUM];
__device__ float g_row_gate[R_NUM];
__device__ int   g_counts[E_NUM];
__device__ int   g_offsets[E_NUM];
__device__ int   g_fill[E_NUM];
__device__ int   g_tok_exp[R_NUM];
__device__ float g_tok_gate[R_NUM];

// ---------------- routing (atomic-free route; fused count+prefix) ----------------
__global__ void k_route(const float* __restrict__ logits) {
    int t = blockIdx.x * blockDim.x + threadIdx.x;
    if (t >= T_TOK) return;
    float v[E_NUM];
    float mx = -1e30f;
#pragma unroll
    for (int e = 0; e < E_NUM; e++) { v[e] = logits[t * E_NUM + e]; mx = fmaxf(mx, v[e]); }
#pragma unroll
    for (int e = 0; e < E_NUM; e++) v[e] = __expf(v[e] - mx);
    int e1 = 0;
#pragma unroll
    for (int e = 1; e < E_NUM; e++) if (v[e] > v[e1]) e1 = e;
    int e2 = (e1 == 0) ? 1 : 0;
#pragma unroll
    for (int e = 0; e < E_NUM; e++) if (e != e1 && v[e] > v[e2]) e2 = e;
    float p1 = v[e1], p2 = v[e2];
    float inv = 1.0f / (p1 + p2);
    g_tok_exp[2 * t] = e1;  g_tok_exp[2 * t + 1] = e2;
    g_tok_gate[2 * t] = p1 * inv; g_tok_gate[2 * t + 1] = p2 * inv;
}

__global__ void k_count_prefix() {
    __shared__ int sc[E_NUM];
    int tid = threadIdx.x;
    if (tid < E_NUM) sc[tid] = 0;
    __syncthreads();
    for (int i = tid; i < R_NUM; i += blockDim.x)
        atomicAdd(&sc[g_tok_exp[i]], 1);
    __syncthreads();
    if (tid == 0) {
        int acc = 0;
        for (int e = 0; e < E_NUM; e++) { g_counts[e] = sc[e]; g_offsets[e] = acc; acc += sc[e]; }
    }
    if (tid < E_NUM) g_fill[tid] = 0;
}

__global__ void k_scatter() {
    int t = blockIdx.x * blockDim.x + threadIdx.x;
    if (t >= T_TOK) return;
#pragma unroll
    for (int s = 0; s < TOPK; s++) {
        int e = g_tok_exp[2 * t + s];
        int pos = g_offsets[e] + atomicAdd(&g_fill[e], 1);
        g_row_token[pos] = t;
        g_row_gate[pos] = g_tok_gate[2 * t + s];
    }
}

// ---------------- tf32 helpers ----------------
__device__ __forceinline__ float f2tf(float x) {
    uint32_t u;
    asm("cvt.rna.tf32.f32 %0, %1;" : "=r"(u) : "f"(x));
    return __uint_as_float(u);
}

__device__ __forceinline__ void sts_seg(float* S, int m, int s, float4 v) {
    int b = (m & 7) * 16 + (m >> 3);
    S[(s * 4 + 0) * AS_STRIDE + b] = f2tf(v.x);
    S[(s * 4 + 1) * AS_STRIDE + b] = f2tf(v.y);
    S[(s * 4 + 2) * AS_STRIDE + b] = f2tf(v.z);
    S[(s * 4 + 3) * AS_STRIDE + b] = f2tf(v.w);
}

#define MMA_TF32(ac, aa, bb)                                                     \
    asm volatile(                                                                \
        "mma.sync.aligned.m16n8k8.row.col.f32.tf32.tf32.f32 "                    \
        "{%0,%1,%2,%3},{%4,%5,%6,%7},{%8,%9},{%0,%1,%2,%3};"                     \
        : "+f"(ac[0]), "+f"(ac[1]), "+f"(ac[2]), "+f"(ac[3])                     \
        : "r"(aa[0]), "r"(aa[1]), "r"(aa[2]), "r"(aa[3]), "r"(bb[0]), "r"(bb[1]))

__device__ __forceinline__ void compute_stage(const float* SA_, const float* SB_,
                                              int lr, int cg, int wm, int wn,
                                              float acc[4][4][4]) {
#pragma unroll
    for (int kk = 0; kk < 2; kk++) {
        uint32_t a[4][4];
        uint32_t b[4][2];
#pragma unroll
        for (int p = 0; p < 2; p++) {
            const float4* ap = reinterpret_cast<const float4*>(
                SA_ + (kk * 8 + p * 4 + cg) * AS_STRIDE + lr * 16 + wm * 8);
            float4 v0 = ap[0], v1 = ap[1];
            a[0][p * 2 + 0] = __float_as_uint(v0.x);
            a[0][p * 2 + 1] = __float_as_uint(v0.y);
            a[1][p * 2 + 0] = __float_as_uint(v0.z);
            a[1][p * 2 + 1] = __float_as_uint(v0.w);
            a[2][p * 2 + 0] = __float_as_uint(v1.x);
            a[2][p * 2 + 1] = __float_as_uint(v1.y);
            a[3][p * 2 + 0] = __float_as_uint(v1.z);
            a[3][p * 2 + 1] = __float_as_uint(v1.w);
        }
#pragma unroll
        for (int p = 0; p < 2; p++) {
            const float4 w = *reinterpret_cast<const float4*>(
                SB_ + (kk * 8 + p * 4 + cg) * AS_STRIDE + lr * 16 + wn * 4);
            b[0][p] = __float_as_uint(w.x);
            b[1][p] = __float_as_uint(w.y);
            b[2][p] = __float_as_uint(w.z);
            b[3][p] = __float_as_uint(w.w);
        }
#pragma unroll
        for (int mt = 0; mt < 4; mt++)
#pragma unroll
            for (int nt = 0; nt < 4; nt++)
                MMA_TF32(acc[mt][nt], a[mt], b[nt]);
    }
}

// ---------------- GEMM1: h = silu(x@Wg^T) * (x@Wu^T), fused epilogue ----------------
// B tile: 128 smem rows = 16 blocks of 8; block b: pair=b>>1, isup=b&1.
// Weight row = i0 + pair*8 + w  (+I_DIM if up).  Warp wn holds blocks 4wn..4wn+3,
// so acc[mt][2q] (gate) and acc[mt][2q+1] (up) pair up in-thread for silu*u.
__global__ __launch_bounds__(256, 2) void k_gemm1(const float* __restrict__ x,
                                                  const float* __restrict__ w13) {
    const int e = blockIdx.z;
    const int cnt = g_counts[e];
    const int rowt = blockIdx.x * BM;
    if (rowt >= cnt) return;
    const int base = g_offsets[e];
    const int i0 = blockIdx.y * 64;

    __shared__ float SA[2][BK * AS_STRIDE];
    __shared__ float SB[2][BK * AS_STRIDE];

    const int tid = threadIdx.x;
    const int am = tid & 127;
    const int sq = tid >> 7;

    const int rowA = rowt + am;
    const bool av = rowA < cnt;
    const float* aptr = x + (size_t)(av ? g_row_token[base + rowA] : 0) * H_DIM;

    const int blk = am >> 3, w = am & 7;
    const int pair = blk >> 1, isup = blk & 1;
    const int wr = i0 + pair * 8 + w + (isup ? I_DIM : 0);
    const float* bptr = w13 + (size_t)e * N2I * H_DIM + (size_t)wr * H_DIM;

    const int lane = tid & 31, wid = tid >> 5;
    const int lr = lane >> 2, cg = lane & 3;
    const int wm = wid >> 2, wn = wid & 3;

    float acc[4][4][4];
#pragma unroll
    for (int mt = 0; mt < 4; mt++)
#pragma unroll
        for (int nt = 0; nt < 4; nt++)
#pragma unroll
            for (int c = 0; c < 4; c++) acc[mt][nt][c] = 0.f;

    const int NK = H_DIM / BK;
    float4 va0, va1, vb0, vb1;
    {
        const float4 z = make_float4(0, 0, 0, 0);
        va0 = av ? *(const float4*)(aptr + sq * 4) : z;
        va1 = av ? *(const float4*)(aptr + (sq + 2) * 4) : z;
        vb0 = *(const float4*)(bptr + sq * 4);
        vb1 = *(const float4*)(bptr + (sq + 2) * 4);
        sts_seg(SA[0], am, sq, va0);  sts_seg(SA[0], am, sq + 2, va1);
        sts_seg(SB[0], am, sq, vb0);  sts_seg(SB[0], am, sq + 2, vb1);
    }
    __syncthreads();

    for (int it = 0; it < NK; it++) {
        if (it + 1 < NK) {
            const int k0 = (it + 1) * BK;
            const float4 z = make_float4(0, 0, 0, 0);
            va0 = av ? *(const float4*)(aptr + k0 + sq * 4) : z;
            va1 = av ? *(const float4*)(aptr + k0 + (sq + 2) * 4) : z;
            vb0 = *(const float4*)(bptr + k0 + sq * 4);
            vb1 = *(const float4*)(bptr + k0 + (sq + 2) * 4);
        }
        compute_stage(SA[it & 1], SB[it & 1], lr, cg, wm, wn, acc);
        __syncthreads();
        if (it + 1 < NK) {
            const int nb = (it + 1) & 1;
            sts_seg(SA[nb], am, sq, va0);  sts_seg(SA[nb], am, sq + 2, va1);
            sts_seg(SB[nb], am, sq, vb0);  sts_seg(SB[nb], am, sq + 2, vb1);
            __syncthreads();
        }
    }

    // fused epilogue: h = silu(g)*u, 64 i-cols per CTA
#pragma unroll
    for (int mt = 0; mt < 4; mt++) {
#pragma unroll
        for (int rr = 0; rr < 2; rr++) {
            const int r = rowt + wm * 64 + mt * 16 + lr + rr * 8;
            if (r < cnt) {
                float* hrow = g_h + (size_t)(base + r) * I_DIM;
#pragma unroll
                for (int q = 0; q < 2; q++) {
                    const float g0 = acc[mt][2 * q][rr * 2 + 0];
                    const float g1 = acc[mt][2 * q][rr * 2 + 1];
                    const float u0 = acc[mt][2 * q + 1][rr * 2 + 0];
                    const float u1 = acc[mt][2 * q + 1][rr * 2 + 1];
                    float2 h;
                    h.x = (g0 / (1.f + __expf(-g0))) * u0;
                    h.y = (g1 / (1.f + __expf(-g1))) * u1;
                    *(float2*)(hrow + i0 + (wn * 2 + q) * 8 + cg * 2) = h;
                }
            }
        }
    }
}

// ---------------- GEMM2: out[token] += gate * (h @ w2^T) ----------------
__global__ __launch_bounds__(256, 2) void k_gemm2(const float* __restrict__ w2,
                                                  float* __restrict__ out) {
    const int e = blockIdx.z;
    const int cnt = g_counts[e];
    const int rowt = blockIdx.x * BM;
    if (rowt >= cnt) return;
    const int base = g_offsets[e];
    const int n0 = blockIdx.y * BN;

    __shared__ float SA[2][BK * AS_STRIDE];
    __shared__ float SB[2][BK * AS_STRIDE];

    const int tid = threadIdx.x;
    const int am = tid & 127;
    const int sq = tid >> 7;

    const int rowA = min(rowt + am, cnt - 1);
    const float* aptr = g_h + (size_t)(base + rowA) * I_DIM;
    const float* bptr = w2 + (size_t)e * H_DIM * I_DIM + (size_t)(n0 + am) * I_DIM;

    const int lane = tid & 31, wid = tid >> 5;
    const int lr = lane >> 2, cg = lane & 3;
    const int wm = wid >> 2, wn = wid & 3;

    float acc[4][4][4];
#pragma unroll
    for (int mt = 0; mt < 4; mt++)
#pragma unroll
        for (int nt = 0; nt < 4; nt++)
#pragma unroll
            for (int c = 0; c < 4; c++) acc[mt][nt][c] = 0.f;

    const int NK = I_DIM / BK;
    float4 va0, va1, vb0, vb1;
    {
        va0 = *(const float4*)(aptr + sq * 4);
        va1 = *(const float4*)(aptr + (sq + 2) * 4);
        vb0 = *(const float4*)(bptr + sq * 4);
        vb1 = *(const float4*)(bptr + (sq + 2) * 4);
        sts_seg(SA[0], am, sq, va0);  sts_seg(SA[0], am, sq + 2, va1);
        sts_seg(SB[0], am, sq, vb0);  sts_seg(SB[0], am, sq + 2, vb1);
    }
    __syncthreads();

    for (int it = 0; it < NK; it++) {
        if (it + 1 < NK) {
            const int k0 = (it + 1) * BK;
            va0 = *(const float4*)(aptr + k0 + sq * 4);
            va1 = *(const float4*)(aptr + k0 + (sq + 2) * 4);
            vb0 = *(const float4*)(bptr + k0 + sq * 4);
            vb1 = *(const float4*)(bptr + k0 + (sq + 2) * 4);
        }
        compute_stage(SA[it & 1], SB[it & 1], lr, cg, wm, wn, acc);
        __syncthreads();
        if (it + 1 < NK) {
            const int nb = (it + 1) & 1;
            sts_seg(SA[nb], am, sq, va0);  sts_seg(SA[nb], am, sq + 2, va1);
            sts_seg(SB[nb], am, sq, vb0);  sts_seg(SB[nb], am, sq + 2, vb1);
            __syncthreads();
        }
    }

#pragma unroll
    for (int mt = 0; mt < 4; mt++) {
        const int r0 = rowt + wm * 64 + mt * 16 + lr;
#pragma unroll
        for (int rr = 0; rr < 2; rr++) {
            const int r = r0 + rr * 8;
            if (r < cnt) {
                const int token = g_row_token[base + r];
                const float gate = g_row_gate[base + r];
                float* po = out + (size_t)token * H_DIM;
#pragma unroll
                for (int nt = 0; nt < 4; nt++) {
                    const int col = n0 + wn * 32 + nt * 8 + cg * 2;
                    atomicAdd(po + col,     gate * acc[mt][nt][rr * 2 + 0]);
                    atomicAdd(po + col + 1, gate * acc[mt][nt][rr * 2 + 1]);
                }
            }
        }
    }
}

// ---------------- launch ----------------
extern "C" void kernel_launch(void* const* d_in, const int* in_sizes, int n_in,
                              void* d_out, int out_size) {
    const float* x      = (const float*)d_in[0];
    const float* logits = (const float*)d_in[1];
    const float* w13    = (const float*)d_in[2];
    const float* w2     = (const float*)d_in[3];
    float* out = (float*)d_out;
    (void)in_sizes; (void)n_in;

    cudaMemsetAsync(out, 0, (size_t)out_size * sizeof(float));
    k_route<<<T_TOK / 256, 256>>>(logits);
    k_count_prefix<<<1, 256>>>();
    k_scatter<<<T_TOK / 256, 256>>>();

    dim3 g1(R_NUM / BM, I_DIM / 64, E_NUM);    // 32 x 88 x 8
    k_gemm1<<<g1, 256>>>(x, w13);

    dim3 g2(R_NUM / BM, H_DIM / BN, E_NUM);    // 32 x 16 x 8
    k_gemm2<<<g2, 256>>>(w2, out);
}

// round 5
// speedup vs baseline: 1.9339x; 1.3907x over previous
#include <cuda_runtime.h>
#include <math.h>
#include <stdint.h>

// Problem constants
#define T_TOK 2048
#define H_DIM 2048
#define E_NUM 8
#define I_DIM 5632
#define N2I   (2 * I_DIM)
#define TOPK  2
#define R_NUM (T_TOK * TOPK)

// Tiling: CTA 128x256x16, 8 warps, warp tile 64x64
#define BM 128
#define BN 256
#define BK 16
#define KSTR 132                      // floats per k-line (128 + 4 pad)
#define TILE_F (BK * KSTR)            // 2112 floats per 128-row tile
#define SMEM_BYTES (2 * 3 * TILE_F * 4)   // 50688 bytes (A,B0,B1 x 2 stages)

// ---------------- device scratch ----------------
__device__ float g_h[(size_t)R_NUM * I_DIM];
__device__ int   g_row_token[R_NUM];
__device__ float g_row_gate[R_NUM];
__device__ int   g_counts[E_NUM];
__device__ int   g_offsets[E_NUM];
__device__ int   g_fill[E_NUM];
__device__ int   g_tok_exp[R_NUM];
__device__ float g_tok_gate[R_NUM];

// ---------------- routing ----------------
__global__ void k_route(const float* __restrict__ logits) {
    int t = blockIdx.x * blockDim.x + threadIdx.x;
    if (t >= T_TOK) return;
    float v[E_NUM];
    float mx = -1e30f;
#pragma unroll
    for (int e = 0; e < E_NUM; e++) { v[e] = logits[t * E_NUM + e]; mx = fmaxf(mx, v[e]); }
#pragma unroll
    for (int e = 0; e < E_NUM; e++) v[e] = __expf(v[e] - mx);
    int e1 = 0;
#pragma unroll
    for (int e = 1; e < E_NUM; e++) if (v[e] > v[e1]) e1 = e;
    int e2 = (e1 == 0) ? 1 : 0;
#pragma unroll
    for (int e = 0; e < E_NUM; e++) if (e != e1 && v[e] > v[e2]) e2 = e;
    float p1 = v[e1], p2 = v[e2];
    float inv = 1.0f / (p1 + p2);
    g_tok_exp[2 * t] = e1;  g_tok_exp[2 * t + 1] = e2;
    g_tok_gate[2 * t] = p1 * inv; g_tok_gate[2 * t + 1] = p2 * inv;
}

__global__ void k_count_prefix() {
    __shared__ int sc[E_NUM];
    int tid = threadIdx.x;
    if (tid < E_NUM) sc[tid] = 0;
    __syncthreads();
    for (int i = tid; i < R_NUM; i += blockDim.x)
        atomicAdd(&sc[g_tok_exp[i]], 1);
    __syncthreads();
    if (tid == 0) {
        int acc = 0;
        for (int e = 0; e < E_NUM; e++) { g_counts[e] = sc[e]; g_offsets[e] = acc; acc += sc[e]; }
    }
    if (tid < E_NUM) g_fill[tid] = 0;
}

__global__ void k_scatter() {
    int t = blockIdx.x * blockDim.x + threadIdx.x;
    if (t >= T_TOK) return;
#pragma unroll
    for (int s = 0; s < TOPK; s++) {
        int e = g_tok_exp[2 * t + s];
        int pos = g_offsets[e] + atomicAdd(&g_fill[e], 1);
        g_row_token[pos] = t;
        g_row_gate[pos] = g_tok_gate[2 * t + s];
    }
}

// ---------------- tf32 helpers ----------------
__device__ __forceinline__ float f2tf(float x) {
    uint32_t u;
    asm("cvt.rna.tf32.f32 %0, %1;" : "=r"(u) : "f"(x));
    return __uint_as_float(u);
}

// write 4 consecutive k-values of one row (k-major layout, permuted row index b)
__device__ __forceinline__ void sts4(float* S, int kbase, int b, float4 v) {
    S[(kbase + 0) * KSTR + b] = f2tf(v.x);
    S[(kbase + 1) * KSTR + b] = f2tf(v.y);
    S[(kbase + 2) * KSTR + b] = f2tf(v.z);
    S[(kbase + 3) * KSTR + b] = f2tf(v.w);
}

#define MMA_TF32(ac, aa, bb)                                                     \
    asm volatile(                                                                \
        "mma.sync.aligned.m16n8k8.row.col.f32.tf32.tf32.f32 "                    \
        "{%0,%1,%2,%3},{%4,%5,%6,%7},{%8,%9},{%0,%1,%2,%3};"                     \
        : "+f"(ac[0]), "+f"(ac[1]), "+f"(ac[2]), "+f"(ac[3])                     \
        : "r"(aa[0]), "r"(aa[1]), "r"(aa[2]), "r"(aa[3]), "r"(bb[0]), "r"(bb[1]))

// one BK=16 stage of a 64x64 warp tile
__device__ __forceinline__ void compute_stage(const float* SA, const float* SBw,
                                              int lr, int cg, int wm, int wnl,
                                              float acc[4][8][4]) {
#pragma unroll
    for (int kk = 0; kk < 2; kk++) {
        uint32_t a[4][4];
        uint32_t b[8][2];
#pragma unroll
        for (int p = 0; p < 2; p++) {
            const int kl = kk * 8 + p * 4 + cg;
            const float4* ap = reinterpret_cast<const float4*>(
                SA + kl * KSTR + lr * 16 + wm * 8);
            float4 v0 = ap[0], v1 = ap[1];
            a[0][p * 2 + 0] = __float_as_uint(v0.x);
            a[0][p * 2 + 1] = __float_as_uint(v0.y);
            a[1][p * 2 + 0] = __float_as_uint(v0.z);
            a[1][p * 2 + 1] = __float_as_uint(v0.w);
            a[2][p * 2 + 0] = __float_as_uint(v1.x);
            a[2][p * 2 + 1] = __float_as_uint(v1.y);
            a[3][p * 2 + 0] = __float_as_uint(v1.z);
            a[3][p * 2 + 1] = __float_as_uint(v1.w);
            const float* bl = SBw + kl * KSTR + lr * 16 + wnl * 8;
            float4 w0 = *reinterpret_cast<const float4*>(bl);
            float4 w1 = *reinterpret_cast<const float4*>(bl + 4);
            b[0][p] = __float_as_uint(w0.x);
            b[1][p] = __float_as_uint(w0.y);
            b[2][p] = __float_as_uint(w0.z);
            b[3][p] = __float_as_uint(w0.w);
            b[4][p] = __float_as_uint(w1.x);
            b[5][p] = __float_as_uint(w1.y);
            b[6][p] = __float_as_uint(w1.z);
            b[7][p] = __float_as_uint(w1.w);
        }
#pragma unroll
        for (int mt = 0; mt < 4; mt++)
#pragma unroll
            for (int nt = 0; nt < 8; nt++)
                MMA_TF32(acc[mt][nt], a[mt], b[nt]);
    }
}

// ---------------- fused GEMM (G=1: x@w13^T + silu*u -> g_h ; G=2: h@w2^T -> out) ----------------
template <int G>
__global__ __launch_bounds__(256, 1) void k_gemm(const float* __restrict__ x,
                                                 const float* __restrict__ W,
                                                 float* __restrict__ out) {
    const int e = blockIdx.z;
    const int cnt = g_counts[e];
    const int rowt = blockIdx.x * BM;
    if (rowt >= cnt) return;
    const int base = g_offsets[e];
    const int i0 = blockIdx.y * 128;   // G==1: 128 i per CTA (256 interleaved gate/up cols)
    const int n0 = blockIdx.y * BN;    // G==2

    extern __shared__ float smem[];

    const int tid = threadIdx.x;
    const int lane = tid & 31, wid = tid >> 5;
    const int q = lane & 15, wpr = lane >> 4;

    // ---- loader setup ----
    // B: each warp fills 32 rows (full k16 per lane) of sub-tile tileB.
    //    bank-perfect: bOff mod 32 = 16*wpr + q  -> all 32 banks per STS instr.
    const int tileB = wid >> 2;                       // 0:cols 0-127, 1:cols 128-255
    const int mB = q * 8 + (wid & 3) * 2 + wpr;       // local row 0..127
    const int bOffB = (mB & 7) * 16 + (mB >> 3);
    const float* bptr;
    if (G == 1) {
        const int gt = tileB * 16 + (mB >> 3);        // global n8-tile 0..31
        const int wr = i0 + (gt >> 1) * 8 + (mB & 7) + (gt & 1) * I_DIM;
        bptr = W + (size_t)e * N2I * H_DIM + (size_t)wr * H_DIM;
    } else {
        const int wr = n0 + tileB * 128 + (mB >> 3) * 8 + (mB & 7);
        bptr = W + (size_t)e * H_DIM * I_DIM + (size_t)wr * I_DIM;
    }
    // A: each warp fills 16 rows, 2 lanes per row (8 k-floats each).
    const int mA = q * 8 + wid;                       // row 0..127 (wid = m&7)
    const int bOffA = wid * 16 + q;
    const int segA = wpr * 8;                         // k-float base within 16
    const float* aptr;
    bool av;
    if (G == 1) {
        const int r = rowt + mA;
        av = r < cnt;
        const int tok = av ? g_row_token[base + r] : 0;
        aptr = x + (size_t)tok * H_DIM + segA;
    } else {
        const int r = min(rowt + mA, cnt - 1);
        av = true;
        aptr = g_h + (size_t)(base + r) * I_DIM + segA;
    }

    // ---- compute-side ids ----
    const int lr = lane >> 2, cg = lane & 3;
    const int wm = wid >> 2;        // 0..1 : 64-row half
    const int wn = wid & 3;         // 0..3 : 64-col slice
    const int wnl = wn & 1;

    float acc[4][8][4];
#pragma unroll
    for (int mt = 0; mt < 4; mt++)
#pragma unroll
        for (int nt = 0; nt < 8; nt++)
#pragma unroll
            for (int c = 0; c < 4; c++) acc[mt][nt][c] = 0.f;

    const int NK = (G == 1 ? H_DIM : I_DIM) / BK;
    const float4 z4 = make_float4(0, 0, 0, 0);
    float4 vb[4], va[2];

    // prologue: load + store stage 0
#pragma unroll
    for (int s = 0; s < 4; s++) vb[s] = __ldg((const float4*)(bptr + s * 4));
    va[0] = av ? __ldg((const float4*)(aptr)) : z4;
    va[1] = av ? __ldg((const float4*)(aptr + 4)) : z4;
    {
        float* S = smem;
        float* SBt = S + TILE_F * (1 + tileB);
#pragma unroll
        for (int s = 0; s < 4; s++) sts4(SBt, s * 4, bOffB, vb[s]);
        sts4(S, segA, bOffA, va[0]);
        sts4(S, segA + 4, bOffA, va[1]);
    }
    __syncthreads();

    for (int it = 0; it < NK; it++) {
        if (it + 1 < NK) {
            const int k0 = (it + 1) * BK;
#pragma unroll
            for (int s = 0; s < 4; s++) vb[s] = __ldg((const float4*)(bptr + k0 + s * 4));
            va[0] = av ? __ldg((const float4*)(aptr + k0)) : z4;
            va[1] = av ? __ldg((const float4*)(aptr + k0 + 4)) : z4;
        }
        {
            const float* S = smem + (it & 1) * (3 * TILE_F);
            const float* SBw = S + TILE_F * (1 + (wn >> 1));
            compute_stage(S, SBw, lr, cg, wm, wnl, acc);
        }
        __syncthreads();
        if (it + 1 < NK) {
            float* S = smem + ((it + 1) & 1) * (3 * TILE_F);
            float* SBt = S + TILE_F * (1 + tileB);
#pragma unroll
            for (int s = 0; s < 4; s++) sts4(SBt, s * 4, bOffB, vb[s]);
            sts4(S, segA, bOffA, va[0]);
            sts4(S, segA + 4, bOffA, va[1]);
            __syncthreads();
        }
    }

    // ---- epilogues ----
    if (G == 1) {
        const int wcol2 = (wn >> 1) * 8 + (wn & 1) * 4;   // i8-tile base within CTA
#pragma unroll
        for (int mt = 0; mt < 4; mt++) {
#pragma unroll
            for (int rr = 0; rr < 2; rr++) {
                const int r = rowt + wm * 64 + mt * 16 + rr * 8 + lr;
                if (r < cnt) {
                    float* hrow = g_h + (size_t)(base + r) * I_DIM + i0;
#pragma unroll
                    for (int q2 = 0; q2 < 4; q2++) {
                        const float g0 = acc[mt][2 * q2][rr * 2 + 0];
                        const float g1 = acc[mt][2 * q2][rr * 2 + 1];
                        const float u0 = acc[mt][2 * q2 + 1][rr * 2 + 0];
                        const float u1 = acc[mt][2 * q2 + 1][rr * 2 + 1];
                        float2 h;
                        h.x = (g0 / (1.f + __expf(-g0))) * u0;
                        h.y = (g1 / (1.f + __expf(-g1))) * u1;
                        *(float2*)(hrow + (wcol2 + q2) * 8 + cg * 2) = h;
                    }
                }
            }
        }
    } else {
        const int wcol = (wn >> 1) * 16 + (wn & 1) * 8;   // n8-tile base within CTA
#pragma unroll
        for (int mt = 0; mt < 4; mt++) {
#pragma unroll
            for (int rr = 0; rr < 2; rr++) {
                const int r = rowt + wm * 64 + mt * 16 + rr * 8 + lr;
                if (r < cnt) {
                    const int token = g_row_token[base + r];
                    const float gate = g_row_gate[base + r];
                    float* po = out + (size_t)token * H_DIM + n0;
#pragma unroll
                    for (int nt = 0; nt < 8; nt++) {
                        const int col = (wcol + nt) * 8 + cg * 2;
                        atomicAdd(po + col,     gate * acc[mt][nt][rr * 2 + 0]);
                        atomicAdd(po + col + 1, gate * acc[mt][nt][rr * 2 + 1]);
                    }
                }
            }
        }
    }
}

// ---------------- launch ----------------
extern "C" void kernel_launch(void* const* d_in, const int* in_sizes, int n_in,
                              void* d_out, int out_size) {
    const float* x      = (const float*)d_in[0];
    const float* logits = (const float*)d_in[1];
    const float* w13    = (const float*)d_in[2];
    const float* w2     = (const float*)d_in[3];
    float* out = (float*)d_out;
    (void)in_sizes; (void)n_in;

    cudaFuncSetAttribute(k_gemm<1>, cudaFuncAttributeMaxDynamicSharedMemorySize, SMEM_BYTES);
    cudaFuncSetAttribute(k_gemm<2>, cudaFuncAttributeMaxDynamicSharedMemorySize, SMEM_BYTES);

    cudaMemsetAsync(out, 0, (size_t)out_size * sizeof(float));
    k_route<<<T_TOK / 256, 256>>>(logits);
    k_count_prefix<<<1, 256>>>();
    k_scatter<<<T_TOK / 256, 256>>>();

    dim3 g1(R_NUM / BM, I_DIM / 128, E_NUM);   // 32 x 44 x 8 (row CTAs early-exit)
    k_gemm<1><<<g1, 256, SMEM_BYTES>>>(x, w13, nullptr);

    dim3 g2(R_NUM / BM, H_DIM / BN, E_NUM);    // 32 x 8 x 8
    k_gemm<2><<<g2, 256, SMEM_BYTES>>>(nullptr, w2, out);
}

// round 6
// speedup vs baseline: 2.1887x; 1.1318x over previous
#include <cuda_runtime.h>
#include <math.h>
#include <stdint.h>

// Problem constants
#define T_TOK 2048
#define H_DIM 2048
#define E_NUM 8
#define I_DIM 5632
#define N2I   (2 * I_DIM)
#define TOPK  2
#define R_NUM (T_TOK * TOPK)

// Tiling: CTA 128x256x32 (fp16), 8 warps, warp tile 64x64
#define BM 128
#define BN 256
#define BK 32
// smem (u32 units): A tile 16 k2 x 128 = 2048, B tile 16 k2 x 256 = 4096
#define A_U32 2048
#define B_U32 4096
#define STG_U32 (A_U32 + B_U32)            // 6144 per stage
#define SMEM_BYTES (2 * STG_U32 * 4)       // 49152

// ---------------- device scratch ----------------
__device__ uint32_t g_h2[(size_t)R_NUM * (I_DIM / 2)];   // h as f16x2 (~46 MB)
__device__ int   g_row_token[R_NUM];
__device__ float g_row_gate[R_NUM];
__device__ int   g_counts[E_NUM];
__device__ int   g_offsets[E_NUM];
__device__ int   g_fill[E_NUM];
__device__ int   g_tok_exp[R_NUM];
__device__ float g_tok_gate[R_NUM];

// ---------------- routing ----------------
__global__ void k_route(const float* __restrict__ logits) {
    int t = blockIdx.x * blockDim.x + threadIdx.x;
    if (t >= T_TOK) return;
    float v[E_NUM];
    float mx = -1e30f;
#pragma unroll
    for (int e = 0; e < E_NUM; e++) { v[e] = logits[t * E_NUM + e]; mx = fmaxf(mx, v[e]); }
#pragma unroll
    for (int e = 0; e < E_NUM; e++) v[e] = __expf(v[e] - mx);
    int e1 = 0;
#pragma unroll
    for (int e = 1; e < E_NUM; e++) if (v[e] > v[e1]) e1 = e;
    int e2 = (e1 == 0) ? 1 : 0;
#pragma unroll
    for (int e = 0; e < E_NUM; e++) if (e != e1 && v[e] > v[e2]) e2 = e;
    float p1 = v[e1], p2 = v[e2];
    float inv = 1.0f / (p1 + p2);
    g_tok_exp[2 * t] = e1;  g_tok_exp[2 * t + 1] = e2;
    g_tok_gate[2 * t] = p1 * inv; g_tok_gate[2 * t + 1] = p2 * inv;
}

__global__ void k_count_prefix() {
    __shared__ int sc[E_NUM];
    int tid = threadIdx.x;
    if (tid < E_NUM) sc[tid] = 0;
    __syncthreads();
    for (int i = tid; i < R_NUM; i += blockDim.x)
        atomicAdd(&sc[g_tok_exp[i]], 1);
    __syncthreads();
    if (tid == 0) {
        int acc = 0;
        for (int e = 0; e < E_NUM; e++) { g_counts[e] = sc[e]; g_offsets[e] = acc; acc += sc[e]; }
    }
    if (tid < E_NUM) g_fill[tid] = 0;
}

__global__ void k_scatter() {
    int t = blockIdx.x * blockDim.x + threadIdx.x;
    if (t >= T_TOK) return;
#pragma unroll
    for (int s = 0; s < TOPK; s++) {
        int e = g_tok_exp[2 * t + s];
        int pos = g_offsets[e] + atomicAdd(&g_fill[e], 1);
        g_row_token[pos] = t;
        g_row_gate[pos] = g_tok_gate[2 * t + s];
    }
}

// ---------------- helpers ----------------
__device__ __forceinline__ uint32_t pack2(float lo, float hi) {
    uint32_t r;
    asm("cvt.rn.f16x2.f32 %0, %1, %2;" : "=r"(r) : "f"(hi), "f"(lo));
    return r;
}

// bank-slot permutation: conflict-free for both STS scatter and fragment LDS
__device__ __forceinline__ int slot8(int j, int k2) {
    return (2 * k2 + ((k2 >> 3) << 2) + j) & 7;
}

#define MMA_F16(ac, a0, a1, a2, a3, b0, b1)                                      \
    asm volatile(                                                                \
        "mma.sync.aligned.m16n8k16.row.col.f32.f16.f16.f32 "                     \
        "{%0,%1,%2,%3},{%4,%5,%6,%7},{%8,%9},{%0,%1,%2,%3};"                     \
        : "+f"(ac[0]), "+f"(ac[1]), "+f"(ac[2]), "+f"(ac[3])                     \
        : "r"(a0), "r"(a1), "r"(a2), "r"(a3), "r"(b0), "r"(b1))

// one BK=32 stage of a 64x64 warp tile (2 x k16 mma steps)
__device__ __forceinline__ void compute_stage(const uint32_t* SA, const uint32_t* SB,
                                              int lr, int cg, int wm, int wn,
                                              float acc[4][8][4]) {
#pragma unroll
    for (int kk = 0; kk < 2; kk++) {
        const int k2lo = kk * 8 + cg, k2hi = k2lo + 4;
        uint32_t alo[2][4], ahi[2][4], blo[2][4], bhi[2][4];
#pragma unroll
        for (int q = 0; q < 2; q++) {
            *(uint4*)alo[q] = *(const uint4*)(SA + k2lo * 128 + (2 * wm + q) * 32 + slot8(lr, k2lo) * 4);
            *(uint4*)ahi[q] = *(const uint4*)(SA + k2hi * 128 + (2 * wm + q) * 32 + slot8(lr, k2hi) * 4);
            *(uint4*)blo[q] = *(const uint4*)(SB + k2lo * 256 + (2 * wn + q) * 32 + slot8(lr, k2lo) * 4);
            *(uint4*)bhi[q] = *(const uint4*)(SB + k2hi * 256 + (2 * wn + q) * 32 + slot8(lr, k2hi) * 4);
        }
#pragma unroll
        for (int qq = 0; qq < 2; qq++)
#pragma unroll
            for (int h = 0; h < 2; h++) {
                const int mt = 2 * qq + h;
                const uint32_t a0 = alo[qq][2 * h], a1 = alo[qq][2 * h + 1];
                const uint32_t a2 = ahi[qq][2 * h], a3 = ahi[qq][2 * h + 1];
#pragma unroll
                for (int qb = 0; qb < 2; qb++)
#pragma unroll
                    for (int j = 0; j < 4; j++)
                        MMA_F16(acc[mt][4 * qb + j], a0, a1, a2, a3, blo[qb][j], bhi[qb][j]);
            }
    }
}

// ---------------- fused GEMM (G=1: x@w13^T + silu*u -> g_h2 ; G=2: h@w2^T -> out) ----------------
template <int G>
__global__ __launch_bounds__(256, 1) void k_gemm(const float* __restrict__ x,
                                                 const float* __restrict__ W,
                                                 float* __restrict__ out) {
    const int e = blockIdx.z;
    const int cnt = g_counts[e];
    const int rowt = blockIdx.x * BM;
    if (rowt >= cnt) return;
    const int base = g_offsets[e];
    const int i0 = blockIdx.y * 128;   // G==1: 128 i per CTA
    const int n0 = blockIdx.y * BN;    // G==2

    extern __shared__ uint32_t sm[];
    const int tid = threadIdx.x;
    const int lane = tid & 31, wid = tid >> 5;
    const int lr = lane >> 2, cg = lane & 3;
    const int wm = wid >> 2, wn = wid & 3;

    // ---- producer setup: A (m = tid&127, khalf = tid>>7) ----
    const int mA = tid & 127, khalf = tid >> 7;
    const int mconstA = ((mA >> 5) << 5) + ((mA >> 3) & 3);
    const int j7A = mA & 7;
    const float* aptrF = nullptr;
    const uint32_t* aptrH = nullptr;
    bool av = true;
    if (G == 1) {
        const int r = rowt + mA;
        av = r < cnt;
        const int tok = av ? g_row_token[base + r] : 0;
        aptrF = x + (size_t)tok * H_DIM + khalf * 16;
    } else {
        const int r = min(rowt + mA, cnt - 1);
        aptrH = g_h2 + (size_t)(base + r) * (I_DIM / 2) + khalf * 8;
    }
    // ---- producer setup: B (n = tid) ----
    const int nB = tid;
    const int mconstB = ((nB >> 5) << 5) + ((nB >> 3) & 3);
    const int j7B = nB & 7;
    const float* bptr;
    if (G == 1) {
        const int gt = nB >> 3;   // even: gate, odd: up (same i-block)
        const int wr = i0 + (gt >> 1) * 8 + (nB & 7) + (gt & 1) * I_DIM;
        bptr = W + (size_t)e * N2I * H_DIM + (size_t)wr * H_DIM;
    } else {
        bptr = W + (size_t)e * H_DIM * I_DIM + (size_t)(n0 + nB) * I_DIM;
    }

    float acc[4][8][4];
#pragma unroll
    for (int mt = 0; mt < 4; mt++)
#pragma unroll
        for (int nt = 0; nt < 8; nt++)
#pragma unroll
            for (int c = 0; c < 4; c++) acc[mt][nt][c] = 0.f;

    const int NK = (G == 1 ? H_DIM : I_DIM) / BK;
    uint32_t pa[8], pb[16];

    // ---- load helpers (macros keep regs in scope) ----
#define LD_A(it_)                                                                \
    do {                                                                         \
        if (G == 1) {                                                            \
            _Pragma("unroll")                                                    \
            for (int j = 0; j < 4; j++) {                                        \
                float4 v = av ? __ldg((const float4*)(aptrF + (it_) * 32 + j * 4)) \
                              : make_float4(0, 0, 0, 0);                         \
                pa[2 * j] = pack2(v.x, v.y);                                     \
                pa[2 * j + 1] = pack2(v.z, v.w);                                 \
            }                                                                    \
        } else {                                                                 \
            *(uint4*)(pa + 0) = __ldg((const uint4*)(aptrH + (it_) * 16));       \
            *(uint4*)(pa + 4) = __ldg((const uint4*)(aptrH + (it_) * 16 + 4));   \
        }                                                                        \
    } while (0)

#define LD_B(it_)                                                                \
    do {                                                                         \
        _Pragma("unroll")                                                        \
        for (int j = 0; j < 8; j++) {                                            \
            float4 v = __ldg((const float4*)(bptr + (it_) * 32 + j * 4));        \
            pb[2 * j] = pack2(v.x, v.y);                                         \
            pb[2 * j + 1] = pack2(v.z, v.w);                                     \
        }                                                                        \
    } while (0)

#define STS_STAGE(S_)                                                            \
    do {                                                                         \
        uint32_t* SA_ = (S_);                                                    \
        uint32_t* SB_ = (S_) + A_U32;                                            \
        _Pragma("unroll")                                                        \
        for (int j = 0; j < 4; j++) {                                            \
            _Pragma("unroll")                                                    \
            for (int p = 0; p < 2; p++) {                                        \
                const int k2 = khalf * 8 + 2 * j + p;                            \
                SA_[k2 * 128 + mconstA + slot8(j7A, k2) * 4] = pa[2 * j + p];    \
            }                                                                    \
        }                                                                        \
        _Pragma("unroll")                                                        \
        for (int j = 0; j < 8; j++) {                                            \
            _Pragma("unroll")                                                    \
            for (int p = 0; p < 2; p++) {                                        \
                const int k2 = 2 * j + p;                                        \
                SB_[k2 * 256 + mconstB + slot8(j7B, k2) * 4] = pb[2 * j + p];    \
            }                                                                    \
        }                                                                        \
    } while (0)

    // prologue
    LD_A(0); LD_B(0);
    STS_STAGE(sm);
    __syncthreads();

    for (int it = 0; it < NK; it++) {
        if (it + 1 < NK) { LD_A(it + 1); LD_B(it + 1); }
        {
            const uint32_t* S = sm + (it & 1) * STG_U32;
            compute_stage(S, S + A_U32, lr, cg, wm, wn, acc);
        }
        __syncthreads();
        if (it + 1 < NK) {
            STS_STAGE(sm + ((it + 1) & 1) * STG_U32);
            __syncthreads();
        }
    }

    // ---- epilogues ----
    if (G == 1) {
#pragma unroll
        for (int mt = 0; mt < 4; mt++) {
#pragma unroll
            for (int rr = 0; rr < 2; rr++) {
                const int r = rowt + wm * 64 + mt * 16 + rr * 8 + lr;
                if (r < cnt) {
                    uint32_t* hrow = g_h2 + (size_t)(base + r) * (I_DIM / 2) + i0 / 2;
#pragma unroll
                    for (int q2 = 0; q2 < 4; q2++) {
                        const float g0 = acc[mt][2 * q2][rr * 2 + 0];
                        const float g1 = acc[mt][2 * q2][rr * 2 + 1];
                        const float u0 = acc[mt][2 * q2 + 1][rr * 2 + 0];
                        const float u1 = acc[mt][2 * q2 + 1][rr * 2 + 1];
                        const float h0 = (g0 / (1.f + __expf(-g0))) * u0;
                        const float h1 = (g1 / (1.f + __expf(-g1))) * u1;
                        hrow[(4 * wn + q2) * 4 + cg] = pack2(h0, h1);
                    }
                }
            }
        }
    } else {
#pragma unroll
        for (int mt = 0; mt < 4; mt++) {
#pragma unroll
            for (int rr = 0; rr < 2; rr++) {
                const int r = rowt + wm * 64 + mt * 16 + rr * 8 + lr;
                if (r < cnt) {
                    const int token = g_row_token[base + r];
                    const float gate = g_row_gate[base + r];
                    float* po = out + (size_t)token * H_DIM + n0 + wn * 64;
#pragma unroll
                    for (int nt = 0; nt < 8; nt++) {
                        const int col = nt * 8 + cg * 2;
                        atomicAdd(po + col,     gate * acc[mt][nt][rr * 2 + 0]);
                        atomicAdd(po + col + 1, gate * acc[mt][nt][rr * 2 + 1]);
                    }
                }
            }
        }
    }
#undef LD_A
#undef LD_B
#undef STS_STAGE
}

// ---------------- launch ----------------
extern "C" void kernel_launch(void* const* d_in, const int* in_sizes, int n_in,
                              void* d_out, int out_size) {
    const float* x      = (const float*)d_in[0];
    const float* logits = (const float*)d_in[1];
    const float* w13    = (const float*)d_in[2];
    const float* w2     = (const float*)d_in[3];
    float* out = (float*)d_out;
    (void)in_sizes; (void)n_in;

    cudaFuncSetAttribute(k_gemm<1>, cudaFuncAttributeMaxDynamicSharedMemorySize, SMEM_BYTES);
    cudaFuncSetAttribute(k_gemm<2>, cudaFuncAttributeMaxDynamicSharedMemorySize, SMEM_BYTES);

    cudaMemsetAsync(out, 0, (size_t)out_size * sizeof(float));
    k_route<<<T_TOK / 256, 256>>>(logits);
    k_count_prefix<<<1, 256>>>();
    k_scatter<<<T_TOK / 256, 256>>>();

    dim3 g1(R_NUM / BM, I_DIM / 128, E_NUM);   // 32 x 44 x 8 (row CTAs early-exit)
    k_gemm<1><<<g1, 256, SMEM_BYTES>>>(x, w13, nullptr);

    dim3 g2(R_NUM / BM, H_DIM / BN, E_NUM);    // 32 x 8 x 8
    k_gemm<2><<<g2, 256, SMEM_BYTES>>>(nullptr, w2, out);
}

// round 12
// speedup vs baseline: 3.2056x; 1.4646x over previous
#include <cuda_runtime.h>
#include <math.h>
#include <stdint.h>

// Problem constants
#define T_TOK 2048
#define H_DIM 2048
#define E_NUM 8
#define I_DIM 5632
#define N2I   (2 * I_DIM)
#define TOPK  2
#define R_NUM (T_TOK * TOPK)

// Tiling: CTA 128x256x32 (fp16), 8 warps, warp tile 64x64 (R6-proven layout)
#define BM 128
#define BN 256
#define BK 32
#define A_U32 2048
#define B_U32 4096
#define STG_U32 (A_U32 + B_U32)            // 6144 per stage
#define NSTAGE 3
#define SMEM_BYTES (NSTAGE * STG_U32 * 4)  // 73728

// ---------------- device scratch ----------------
#define W13H_U32 (E_NUM * N2I * H_DIM / 2)
#define W2H_U32  (E_NUM * H_DIM * I_DIM / 2)
#define XH_U32   (T_TOK * H_DIM / 2)
__device__ uint32_t g_w13h[W13H_U32];                   // fp16 weights (~369 MB)
__device__ uint32_t g_w2h[W2H_U32];                     // (~185 MB)
__device__ uint32_t g_xh[XH_U32];                       // fp16 x (8 MB)
__device__ uint32_t g_h2[(size_t)R_NUM * (I_DIM / 2)];  // fp16 h (~46 MB)
__device__ int   g_row_token[R_NUM];
__device__ float g_row_gate[R_NUM];
__device__ int   g_counts[E_NUM];
__device__ int   g_offsets[E_NUM];
__device__ int   g_fill[E_NUM];
__device__ int   g_tok_exp[R_NUM];
__device__ float g_tok_gate[R_NUM];

// ---------------- routing ----------------
__global__ void k_route(const float* __restrict__ logits) {
    int t = blockIdx.x * blockDim.x + threadIdx.x;
    if (t >= T_TOK) return;
    float v[E_NUM];
    float mx = -1e30f;
#pragma unroll
    for (int e = 0; e < E_NUM; e++) { v[e] = logits[t * E_NUM + e]; mx = fmaxf(mx, v[e]); }
#pragma unroll
    for (int e = 0; e < E_NUM; e++) v[e] = __expf(v[e] - mx);
    int e1 = 0;
#pragma unroll
    for (int e = 1; e < E_NUM; e++) if (v[e] > v[e1]) e1 = e;
    int e2 = (e1 == 0) ? 1 : 0;
#pragma unroll
    for (int e = 0; e < E_NUM; e++) if (e != e1 && v[e] > v[e2]) e2 = e;
    float p1 = v[e1], p2 = v[e2];
    float inv = 1.0f / (p1 + p2);
    g_tok_exp[2 * t] = e1;  g_tok_exp[2 * t + 1] = e2;
    g_tok_gate[2 * t] = p1 * inv; g_tok_gate[2 * t + 1] = p2 * inv;
}

__global__ void k_count_prefix() {
    __shared__ int sc[E_NUM];
    int tid = threadIdx.x;
    if (tid < E_NUM) sc[tid] = 0;
    __syncthreads();
    for (int i = tid; i < R_NUM; i += blockDim.x)
        atomicAdd(&sc[g_tok_exp[i]], 1);
    __syncthreads();
    if (tid == 0) {
        int acc = 0;
        for (int e = 0; e < E_NUM; e++) { g_counts[e] = sc[e]; g_offsets[e] = acc; acc += sc[e]; }
    }
    if (tid < E_NUM) g_fill[tid] = 0;
}

__global__ void k_scatter() {
    int t = blockIdx.x * blockDim.x + threadIdx.x;
    if (t >= T_TOK) return;
#pragma unroll
    for (int s = 0; s < TOPK; s++) {
        int e = g_tok_exp[2 * t + s];
        int pos = g_offsets[e] + atomicAdd(&g_fill[e], 1);
        g_row_token[pos] = t;
        g_row_gate[pos] = g_tok_gate[2 * t + s];
    }
}

// ---------------- helpers ----------------
__device__ __forceinline__ uint32_t pack2(float lo, float hi) {
    uint32_t r;
    asm("cvt.rn.f16x2.f32 %0, %1, %2;" : "=r"(r) : "f"(hi), "f"(lo));
    return r;
}

// f32 -> f16 bulk convert
__global__ __launch_bounds__(256) void k_cvt(const float4* __restrict__ s,
                                             uint2* __restrict__ d, int n4) {
    int i = blockIdx.x * blockDim.x + threadIdx.x;
    if (i >= n4) return;
    float4 v = s[i];
    uint2 o;
    o.x = pack2(v.x, v.y);
    o.y = pack2(v.z, v.w);
    d[i] = o;
}

// R6-proven bank-slot permutation
__device__ __forceinline__ int slot8(int j, int k2) {
    return (2 * k2 + ((k2 >> 3) << 2) + j) & 7;
}

#define MMA_F16(ac, a0, a1, a2, a3, b0, b1)                                      \
    asm volatile(                                                                \
        "mma.sync.aligned.m16n8k16.row.col.f32.f16.f16.f32 "                     \
        "{%0,%1,%2,%3},{%4,%5,%6,%7},{%8,%9},{%0,%1,%2,%3};"                     \
        : "+f"(ac[0]), "+f"(ac[1]), "+f"(ac[2]), "+f"(ac[3])                     \
        : "r"(a0), "r"(a1), "r"(a2), "r"(a3), "r"(b0), "r"(b1))

// one BK=32 stage of a 64x64 warp tile (R6-proven)
__device__ __forceinline__ void compute_stage(const uint32_t* SA, const uint32_t* SB,
                                              int lr, int cg, int wm, int wn,
                                              float acc[4][8][4]) {
#pragma unroll
    for (int kk = 0; kk < 2; kk++) {
        const int k2lo = kk * 8 + cg, k2hi = k2lo + 4;
        uint32_t alo[2][4], ahi[2][4], blo[2][4], bhi[2][4];
#pragma unroll
        for (int q = 0; q < 2; q++) {
            *(uint4*)alo[q] = *(const uint4*)(SA + k2lo * 128 + (2 * wm + q) * 32 + slot8(lr, k2lo) * 4);
            *(uint4*)ahi[q] = *(const uint4*)(SA + k2hi * 128 + (2 * wm + q) * 32 + slot8(lr, k2hi) * 4);
            *(uint4*)blo[q] = *(const uint4*)(SB + k2lo * 256 + (2 * wn + q) * 32 + slot8(lr, k2lo) * 4);
            *(uint4*)bhi[q] = *(const uint4*)(SB + k2hi * 256 + (2 * wn + q) * 32 + slot8(lr, k2hi) * 4);
        }
#pragma unroll
        for (int qq = 0; qq < 2; qq++)
#pragma unroll
            for (int h = 0; h < 2; h++) {
                const int mt = 2 * qq + h;
                const uint32_t a0 = alo[qq][2 * h], a1 = alo[qq][2 * h + 1];
                const uint32_t a2 = ahi[qq][2 * h], a3 = ahi[qq][2 * h + 1];
#pragma unroll
                for (int qb = 0; qb < 2; qb++)
#pragma unroll
                    for (int j = 0; j < 4; j++)
                        MMA_F16(acc[mt][4 * qb + j], a0, a1, a2, a3, blo[qb][j], bhi[qb][j]);
            }
    }
}

// ---------------- fused GEMM (G=1: x@w13^T + silu*u -> g_h2 ; G=2: h@w2^T -> out) ----------------
template <int G>
__global__ __launch_bounds__(256, 1) void k_gemm(const uint32_t* __restrict__ Ah,
                                                 const uint32_t* __restrict__ Bh,
                                                 float* __restrict__ out) {
    const int e = blockIdx.z;
    const int cnt = g_counts[e];
    const int rowt = blockIdx.x * BM;
    if (rowt >= cnt) return;
    const int base = g_offsets[e];
    const int i0 = blockIdx.y * 128;   // G==1: 128 i per CTA
    const int n0 = blockIdx.y * BN;    // G==2

    extern __shared__ uint32_t sm[];
    const int tid = threadIdx.x;
    const int lane = tid & 31, wid = tid >> 5;
    const int lr = lane >> 2, cg = lane & 3;
    const int wm = wid >> 2, wn = wid & 3;

    // ---- producer setup: A (m = tid&127, khalf = tid>>7) ----
    const int mA = tid & 127, khalf = tid >> 7;
    const int mconstA = ((mA >> 5) << 5) + ((mA >> 3) & 3);
    const int j7A = mA & 7;
    const uint32_t* aptrH;
    bool av = true;
    if (G == 1) {
        const int r = rowt + mA;
        av = r < cnt;
        const int tok = av ? g_row_token[base + r] : 0;
        aptrH = Ah + (size_t)tok * (H_DIM / 2) + khalf * 8;
    } else {
        const int r = min(rowt + mA, cnt - 1);
        aptrH = g_h2 + (size_t)(base + r) * (I_DIM / 2) + khalf * 8;
    }
    // ---- producer setup: B (n = tid) ----
    const int nB = tid;
    const int mconstB = ((nB >> 5) << 5) + ((nB >> 3) & 3);
    const int j7B = nB & 7;
    const uint32_t* bptrH;
    if (G == 1) {
        const int gt = nB >> 3;   // even: gate, odd: up (same i-block)
        const int wr = i0 + (gt >> 1) * 8 + (nB & 7) + (gt & 1) * I_DIM;
        // FIX (R7/R10 bug): expert offset was missing
        bptrH = Bh + (size_t)e * N2I * (H_DIM / 2) + (size_t)wr * (H_DIM / 2);
    } else {
        // FIX (R7/R10 bug): expert offset was missing
        bptrH = Bh + (size_t)e * H_DIM * (I_DIM / 2) + (size_t)(n0 + nB) * (I_DIM / 2);
    }

    float acc[4][8][4];
#pragma unroll
    for (int mt = 0; mt < 4; mt++)
#pragma unroll
        for (int nt = 0; nt < 8; nt++)
#pragma unroll
            for (int c = 0; c < 4; c++) acc[mt][nt][c] = 0.f;

    const int NK = (G == 1 ? H_DIM : I_DIM) / BK;
    uint32_t pa[8], pb[16];
    const uint4 z4 = make_uint4(0, 0, 0, 0);

#define LD_AB(it_)                                                               \
    do {                                                                         \
        *(uint4*)(pa + 0) = av ? __ldg((const uint4*)(aptrH + (it_) * 16))     : z4; \
        *(uint4*)(pa + 4) = av ? __ldg((const uint4*)(aptrH + (it_) * 16 + 4)) : z4; \
        _Pragma("unroll")                                                        \
        for (int j = 0; j < 4; j++)                                              \
            *(uint4*)(pb + 4 * j) = __ldg((const uint4*)(bptrH + (it_) * 16 + 4 * j)); \
    } while (0)

#define STS_STAGE(S_)                                                            \
    do {                                                                         \
        uint32_t* SA_ = (S_);                                                    \
        uint32_t* SB_ = (S_) + A_U32;                                            \
        _Pragma("unroll")                                                        \
        for (int j = 0; j < 4; j++) {                                            \
            _Pragma("unroll")                                                    \
            for (int p = 0; p < 2; p++) {                                        \
                const int k2 = khalf * 8 + 2 * j + p;                            \
                SA_[k2 * 128 + mconstA + slot8(j7A, k2) * 4] = pa[2 * j + p];    \
            }                                                                    \
        }                                                                        \
        _Pragma("unroll")                                                        \
        for (int j = 0; j < 8; j++) {                                            \
            _Pragma("unroll")                                                    \
            for (int p = 0; p < 2; p++) {                                        \
                const int k2 = 2 * j + p;                                        \
                SB_[k2 * 256 + mconstB + slot8(j7B, k2) * 4] = pb[2 * j + p];    \
            }                                                                    \
        }                                                                        \
    } while (0)

    // prologue: fill stages 0 and 1
    LD_AB(0); STS_STAGE(sm);
    LD_AB(1); STS_STAGE(sm + STG_U32);
    __syncthreads();

    // main loop: ONE sync per stage
    for (int it = 0; it < NK; it++) {
        const bool pf = (it + 2 < NK);
        if (pf) LD_AB(it + 2);
        {
            const uint32_t* S = sm + (it % NSTAGE) * STG_U32;
            compute_stage(S, S + A_U32, lr, cg, wm, wn, acc);
        }
        if (pf) STS_STAGE(sm + ((it + 2) % NSTAGE) * STG_U32);
        __syncthreads();
    }
#undef LD_AB
#undef STS_STAGE

    // ---- epilogues (R6-proven) ----
    if (G == 1) {
#pragma unroll
        for (int mt = 0; mt < 4; mt++) {
#pragma unroll
            for (int rr = 0; rr < 2; rr++) {
                const int r = rowt + wm * 64 + mt * 16 + rr * 8 + lr;
                if (r < cnt) {
                    uint32_t* hrow = g_h2 + (size_t)(base + r) * (I_DIM / 2) + i0 / 2;
#pragma unroll
                    for (int q2 = 0; q2 < 4; q2++) {
                        const float g0 = acc[mt][2 * q2][rr * 2 + 0];
                        const float g1 = acc[mt][2 * q2][rr * 2 + 1];
                        const float u0 = acc[mt][2 * q2 + 1][rr * 2 + 0];
                        const float u1 = acc[mt][2 * q2 + 1][rr * 2 + 1];
                        const float h0 = (g0 / (1.f + __expf(-g0))) * u0;
                        const float h1 = (g1 / (1.f + __expf(-g1))) * u1;
                        hrow[(4 * wn + q2) * 4 + cg] = pack2(h0, h1);
                    }
                }
            }
        }
    } else {
#pragma unroll
        for (int mt = 0; mt < 4; mt++) {
#pragma unroll
            for (int rr = 0; rr < 2; rr++) {
                const int r = rowt + wm * 64 + mt * 16 + rr * 8 + lr;
                if (r < cnt) {
                    const int token = g_row_token[base + r];
                    const float gate = g_row_gate[base + r];
                    float* po = out + (size_t)token * H_DIM + n0 + wn * 64;
#pragma unroll
                    for (int nt = 0; nt < 8; nt++) {
                        const int col = nt * 8 + cg * 2;
                        atomicAdd(po + col,     gate * acc[mt][nt][rr * 2 + 0]);
                        atomicAdd(po + col + 1, gate * acc[mt][nt][rr * 2 + 1]);
                    }
                }
            }
        }
    }
}

// ---------------- launch ----------------
extern "C" void kernel_launch(void* const* d_in, const int* in_sizes, int n_in,
                              void* d_out, int out_size) {
    const float* x      = (const float*)d_in[0];
    const float* logits = (const float*)d_in[1];
    const float* w13    = (const float*)d_in[2];
    const float* w2     = (const float*)d_in[3];
    float* out = (float*)d_out;
    (void)in_sizes; (void)n_in;

    cudaFuncSetAttribute(k_gemm<1>, cudaFuncAttributeMaxDynamicSharedMemorySize, SMEM_BYTES);
    cudaFuncSetAttribute(k_gemm<2>, cudaFuncAttributeMaxDynamicSharedMemorySize, SMEM_BYTES);

    cudaMemsetAsync(out, 0, (size_t)out_size * sizeof(float));
    k_route<<<T_TOK / 256, 256>>>(logits);
    k_count_prefix<<<1, 256>>>();
    k_scatter<<<T_TOK / 256, 256>>>();

    // fp16 conversion passes
    uint32_t* w13h; cudaGetSymbolAddress((void**)&w13h, g_w13h);
    uint32_t* w2h;  cudaGetSymbolAddress((void**)&w2h,  g_w2h);
    uint32_t* xh;   cudaGetSymbolAddress((void**)&xh,   g_xh);
    const int n4_w13 = W13H_U32 / 2, n4_w2 = W2H_U32 / 2, n4_x = XH_U32 / 2;
    k_cvt<<<(n4_x + 255) / 256, 256>>>((const float4*)x, (uint2*)xh, n4_x);
    k_cvt<<<(n4_w13 + 255) / 256, 256>>>((const float4*)w13, (uint2*)w13h, n4_w13);
    k_cvt<<<(n4_w2 + 255) / 256, 256>>>((const float4*)w2, (uint2*)w2h, n4_w2);

    dim3 g1(R_NUM / BM, I_DIM / 128, E_NUM);   // 32 x 44 x 8 (row CTAs early-exit)
    k_gemm<1><<<g1, 256, SMEM_BYTES>>>(xh, w13h, nullptr);

    dim3 g2(R_NUM / BM, H_DIM / BN, E_NUM);    // 32 x 8 x 8
    k_gemm<2><<<g2, 256, SMEM_BYTES>>>(nullptr, w2h, out);
}

// round 13
// speedup vs baseline: 3.8567x; 1.2031x over previous
#include <cuda_runtime.h>
#include <math.h>
#include <stdint.h>

// Problem constants
#define T_TOK 2048
#define H_DIM 2048
#define E_NUM 8
#define I_DIM 5632
#define N2I   (2 * I_DIM)
#define TOPK  2
#define R_NUM (T_TOK * TOPK)

// Tiling: CTA 128x256x32 (fp16), 8 warps, warp tile 64x64
#define BM 128
#define BN 256
#define BK 32
#define STAGES 4
#define A_BYTES (BM * BK * 2)              // 8192
#define B_BYTES (BN * BK * 2)              // 16384
#define STAGE_BYTES (A_BYTES + B_BYTES)    // 24576
#define SMEM_BYTES (STAGES * STAGE_BYTES)  // 98304

// ---------------- device scratch ----------------
#define W13H_U32 (E_NUM * N2I * H_DIM / 2)
#define W2H_U32  (E_NUM * H_DIM * I_DIM / 2)
#define XH_U32   (T_TOK * H_DIM / 2)
__device__ uint32_t g_w13h[W13H_U32];          // fp16 weights (~369 MB)
__device__ uint32_t g_w2h[W2H_U32];            // (~185 MB)
__device__ uint32_t g_xh[XH_U32];              // fp16 x (8 MB)
__device__ uint32_t g_h2[(size_t)R_NUM * (I_DIM / 2)];  // fp16 h (~46 MB)
__device__ int   g_row_token[R_NUM];
__device__ float g_row_gate[R_NUM];
__device__ int   g_counts[E_NUM];
__device__ int   g_offsets[E_NUM];
__device__ int   g_fill[E_NUM];
__device__ int   g_tok_exp[R_NUM];
__device__ float g_tok_gate[R_NUM];

// ---------------- helpers ----------------
__device__ __forceinline__ uint32_t smem_u32(const void* p) {
    uint32_t a;
    asm("{ .reg .u64 t; cvta.to.shared.u64 t, %1; cvt.u32.u64 %0, t; }" : "=r"(a) : "l"(p));
    return a;
}
__device__ __forceinline__ uint32_t pack2(float lo, float hi) {
    uint32_t r;
    asm("cvt.rn.f16x2.f32 %0, %1, %2;" : "=r"(r) : "f"(hi), "f"(lo));
    return r;
}
// SW64 swizzle on byte offsets (rows of 64B, 16B chunk permutation)
__device__ __forceinline__ uint32_t swz64(uint32_t o) { return o ^ ((o >> 3) & 0x30); }

#define CPA(d, s, z) asm volatile("cp.async.cg.shared.global [%0], [%1], 16, %2;" :: "r"(d), "l"(s), "r"(z))
#define CPC() asm volatile("cp.async.commit_group;" ::: "memory")

#define LDSM4(r, a)                                                              \
    asm volatile("ldmatrix.sync.aligned.m8n8.x4.shared.b16 {%0,%1,%2,%3}, [%4];" \
                 : "=r"((r)[0]), "=r"((r)[1]), "=r"((r)[2]), "=r"((r)[3]) : "r"(a))

#define MMA_F16(ac, A, b0, b1)                                                   \
    asm volatile(                                                                \
        "mma.sync.aligned.m16n8k16.row.col.f32.f16.f16.f32 "                     \
        "{%0,%1,%2,%3},{%4,%5,%6,%7},{%8,%9},{%0,%1,%2,%3};"                     \
        : "+f"((ac)[0]), "+f"((ac)[1]), "+f"((ac)[2]), "+f"((ac)[3])             \
        : "r"((A)[0]), "r"((A)[1]), "r"((A)[2]), "r"((A)[3]), "r"(b0), "r"(b1))

// ---------------- routing ----------------
__global__ void k_route(const float* __restrict__ logits) {
    int t = blockIdx.x * blockDim.x + threadIdx.x;
    if (t >= T_TOK) return;
    float v[E_NUM];
    float mx = -1e30f;
#pragma unroll
    for (int e = 0; e < E_NUM; e++) { v[e] = logits[t * E_NUM + e]; mx = fmaxf(mx, v[e]); }
#pragma unroll
    for (int e = 0; e < E_NUM; e++) v[e] = __expf(v[e] - mx);
    int e1 = 0;
#pragma unroll
    for (int e = 1; e < E_NUM; e++) if (v[e] > v[e1]) e1 = e;
    int e2 = (e1 == 0) ? 1 : 0;
#pragma unroll
    for (int e = 0; e < E_NUM; e++) if (e != e1 && v[e] > v[e2]) e2 = e;
    float p1 = v[e1], p2 = v[e2];
    float inv = 1.0f / (p1 + p2);
    g_tok_exp[2 * t] = e1;  g_tok_exp[2 * t + 1] = e2;
    g_tok_gate[2 * t] = p1 * inv; g_tok_gate[2 * t + 1] = p2 * inv;
}

__global__ void k_count_prefix() {
    __shared__ int sc[E_NUM];
    int tid = threadIdx.x;
    if (tid < E_NUM) sc[tid] = 0;
    __syncthreads();
    for (int i = tid; i < R_NUM; i += blockDim.x)
        atomicAdd(&sc[g_tok_exp[i]], 1);
    __syncthreads();
    if (tid == 0) {
        int acc = 0;
        for (int e = 0; e < E_NUM; e++) { g_counts[e] = sc[e]; g_offsets[e] = acc; acc += sc[e]; }
    }
    if (tid < E_NUM) g_fill[tid] = 0;
}

__global__ void k_scatter() {
    int t = blockIdx.x * blockDim.x + threadIdx.x;
    if (t >= T_TOK) return;
#pragma unroll
    for (int s = 0; s < TOPK; s++) {
        int e = g_tok_exp[2 * t + s];
        int pos = g_offsets[e] + atomicAdd(&g_fill[e], 1);
        g_row_token[pos] = t;
        g_row_gate[pos] = g_tok_gate[2 * t + s];
    }
}

// ---------------- f32 -> f16 convert (bandwidth pass) ----------------
__global__ __launch_bounds__(256) void k_cvt(const float4* __restrict__ s,
                                             uint2* __restrict__ d, int n4) {
    int i = blockIdx.x * blockDim.x + threadIdx.x;
    if (i >= n4) return;
    float4 v = s[i];
    uint2 o;
    o.x = pack2(v.x, v.y);
    o.y = pack2(v.z, v.w);
    d[i] = o;
}

// ---------------- fused GEMM (G=1: x@w13^T + silu*u -> g_h2 ; G=2: h@w2^T -> out) ----------------
template <int G>
__global__ __launch_bounds__(256, 1) void k_gemm(const uint32_t* __restrict__ Ah,
                                                 const uint32_t* __restrict__ Bh,
                                                 float* __restrict__ out) {
    const int e = blockIdx.z;
    const int cnt = g_counts[e];
    const int rowt = blockIdx.x * BM;
    if (rowt >= cnt) return;
    const int base = g_offsets[e];
    const int i0 = blockIdx.y * 128;   // G==1
    const int n0 = blockIdx.y * BN;    // G==2

    extern __shared__ char smem[];
    const uint32_t sb = smem_u32(smem);
    const int tid = threadIdx.x;
    const int lane = tid & 31, wid = tid >> 5;
    const int lr = lane >> 2, cg = lane & 3;
    const int wm = wid >> 2, wn = wid & 3;

    // ---- cp.async producer setup ----
    // A: thread t loads 32B (2 chunks) of row t>>1
    const int rA = tid >> 1;
    const int ch0 = (tid & 1) * 2;
    const uint32_t aDst0 = swz64(rA * 64 + ch0 * 16);
    const uint32_t aDst1 = swz64(rA * 64 + (ch0 + 1) * 16);
    const uint32_t* aSrc;
    uint32_t aSz = 16;
    if (G == 1) {
        const int r = rowt + rA;
        const bool av = r < cnt;
        aSz = av ? 16u : 0u;
        const int tok = av ? g_row_token[base + r] : 0;
        aSrc = Ah + (size_t)tok * (H_DIM / 2) + ch0 * 4;
    } else {
        const int r = min(rowt + rA, cnt - 1);
        aSrc = g_h2 + (size_t)(base + r) * (I_DIM / 2) + ch0 * 4;
    }
    // B: thread t loads 64B (4 chunks) of row t
    uint32_t bDst[4];
#pragma unroll
    for (int j = 0; j < 4; j++) bDst[j] = swz64(tid * 64 + j * 16);
    const uint32_t* bSrc;
    if (G == 1) {
        const int gt = tid >> 3;   // even: gate, odd: up
        const int wr = i0 + (gt >> 1) * 8 + (tid & 7) + (gt & 1) * I_DIM;
        // FIX (R7/R10 bug): expert offset was missing
        bSrc = Bh + (size_t)e * N2I * (H_DIM / 2) + (size_t)wr * (H_DIM / 2);
    } else {
        // FIX (R7/R10 bug): expert offset was missing
        bSrc = Bh + (size_t)e * H_DIM * (I_DIM / 2) + (size_t)(n0 + tid) * (I_DIM / 2);
    }

    // ---- ldmatrix fragment addresses ----
    const int fr = (lane & 7) + ((lane >> 3) & 1) * 8;
    const int fc = lane >> 4;
    uint32_t aoff[4], boff[4];
#pragma unroll
    for (int mt = 0; mt < 4; mt++)
        aoff[mt] = swz64((uint32_t)((wm * 64 + mt * 16 + fr) * 64 + fc * 16));
#pragma unroll
    for (int g = 0; g < 4; g++)
        boff[g] = swz64((uint32_t)((wn * 64 + g * 16 + fr) * 64 + fc * 16));

    float acc[4][8][4];
#pragma unroll
    for (int mt = 0; mt < 4; mt++)
#pragma unroll
        for (int nt = 0; nt < 8; nt++)
#pragma unroll
            for (int c = 0; c < 4; c++) acc[mt][nt][c] = 0.f;

    const int NK = (G == 1 ? H_DIM : I_DIM) / BK;

#define ISSUE(s_, it_)                                                           \
    do {                                                                         \
        const uint32_t sbase = sb + (s_) * STAGE_BYTES;                          \
        const uint32_t* as = aSrc + (it_) * (BK / 2);                            \
        CPA(sbase + aDst0, as, aSz);                                             \
        CPA(sbase + aDst1, as + 4, aSz);                                         \
        const uint32_t* bs = bSrc + (it_) * (BK / 2);                            \
        const uint32_t bb = sbase + A_BYTES;                                     \
        CPA(bb + bDst[0], bs, 16);                                               \
        CPA(bb + bDst[1], bs + 4, 16);                                           \
        CPA(bb + bDst[2], bs + 8, 16);                                           \
        CPA(bb + bDst[3], bs + 12, 16);                                          \
    } while (0)

    // prologue: fill stages 0..STAGES-2
#pragma unroll
    for (int s = 0; s < STAGES - 1; s++) {
        if (s < NK) ISSUE(s, s);
        CPC();
    }

    for (int it = 0; it < NK; it++) {
        asm volatile("cp.async.wait_group %0;" :: "n"(STAGES - 2) : "memory");
        __syncthreads();
        const uint32_t aB = sb + (it % STAGES) * STAGE_BYTES;
        const uint32_t bB = aB + A_BYTES;
#pragma unroll
        for (int kk = 0; kk < 2; kk++) {
            uint32_t A4[4][4], B4[4][4];
#pragma unroll
            for (int mt = 0; mt < 4; mt++) LDSM4(A4[mt], aB + (aoff[mt] ^ (kk * 32)));
#pragma unroll
            for (int g = 0; g < 4; g++) LDSM4(B4[g], bB + (boff[g] ^ (kk * 32)));
#pragma unroll
            for (int mt = 0; mt < 4; mt++)
#pragma unroll
                for (int g = 0; g < 4; g++) {
                    MMA_F16(acc[mt][2 * g],     A4[mt], B4[g][0], B4[g][2]);
                    MMA_F16(acc[mt][2 * g + 1], A4[mt], B4[g][1], B4[g][3]);
                }
        }
        // issue next stage into the slot computed last iteration (safe after the
        // top-of-loop __syncthreads of THIS iteration)
        if (it + STAGES - 1 < NK) ISSUE((it + STAGES - 1) % STAGES, it + STAGES - 1);
        CPC();
    }
#undef ISSUE

    // ---- epilogues (R12-proven) ----
    if (G == 1) {
#pragma unroll
        for (int mt = 0; mt < 4; mt++) {
#pragma unroll
            for (int rr = 0; rr < 2; rr++) {
                const int r = rowt + wm * 64 + mt * 16 + rr * 8 + lr;
                if (r < cnt) {
                    uint32_t* hrow = g_h2 + (size_t)(base + r) * (I_DIM / 2) + i0 / 2;
#pragma unroll
                    for (int q2 = 0; q2 < 4; q2++) {
                        const float g0 = acc[mt][2 * q2][rr * 2 + 0];
                        const float g1 = acc[mt][2 * q2][rr * 2 + 1];
                        const float u0 = acc[mt][2 * q2 + 1][rr * 2 + 0];
                        const float u1 = acc[mt][2 * q2 + 1][rr * 2 + 1];
                        const float h0 = (g0 / (1.f + __expf(-g0))) * u0;
                        const float h1 = (g1 / (1.f + __expf(-g1))) * u1;
                        hrow[(4 * wn + q2) * 4 + cg] = pack2(h0, h1);
                    }
                }
            }
        }
    } else {
#pragma unroll
        for (int mt = 0; mt < 4; mt++) {
#pragma unroll
            for (int rr = 0; rr < 2; rr++) {
                const int r = rowt + wm * 64 + mt * 16 + rr * 8 + lr;
                if (r < cnt) {
                    const int token = g_row_token[base + r];
                    const float gate = g_row_gate[base + r];
                    float* po = out + (size_t)token * H_DIM + n0 + wn * 64;
#pragma unroll
                    for (int nt = 0; nt < 8; nt++) {
                        const int col = nt * 8 + cg * 2;
                        atomicAdd(po + col,     gate * acc[mt][nt][rr * 2 + 0]);
                        atomicAdd(po + col + 1, gate * acc[mt][nt][rr * 2 + 1]);
                    }
                }
            }
        }
    }
}

// ---------------- launch ----------------
extern "C" void kernel_launch(void* const* d_in, const int* in_sizes, int n_in,
                              void* d_out, int out_size) {
    const float* x      = (const float*)d_in[0];
    const float* logits = (const float*)d_in[1];
    const float* w13    = (const float*)d_in[2];
    const float* w2     = (const float*)d_in[3];
    float* out = (float*)d_out;
    (void)in_sizes; (void)n_in;

    cudaFuncSetAttribute(k_gemm<1>, cudaFuncAttributeMaxDynamicSharedMemorySize, SMEM_BYTES);
    cudaFuncSetAttribute(k_gemm<2>, cudaFuncAttributeMaxDynamicSharedMemorySize, SMEM_BYTES);

    cudaMemsetAsync(out, 0, (size_t)out_size * sizeof(float));
    k_route<<<T_TOK / 256, 256>>>(logits);
    k_count_prefix<<<1, 256>>>();
    k_scatter<<<T_TOK / 256, 256>>>();

    // fp16 conversion passes
    uint32_t* w13h; cudaGetSymbolAddress((void**)&w13h, g_w13h);
    uint32_t* w2h;  cudaGetSymbolAddress((void**)&w2h,  g_w2h);
    uint32_t* xh;   cudaGetSymbolAddress((void**)&xh,   g_xh);
    const int n4_w13 = W13H_U32 / 2, n4_w2 = W2H_U32 / 2, n4_x = XH_U32 / 2;
    k_cvt<<<(n4_x + 255) / 256, 256>>>((const float4*)x, (uint2*)xh, n4_x);
    k_cvt<<<(n4_w13 + 255) / 256, 256>>>((const float4*)w13, (uint2*)w13h, n4_w13);
    k_cvt<<<(n4_w2 + 255) / 256, 256>>>((const float4*)w2, (uint2*)w2h, n4_w2);

    dim3 g1(R_NUM / BM, I_DIM / 128, E_NUM);   // 32 x 44 x 8 (row CTAs early-exit)
    k_gemm<1><<<g1, 256, SMEM_BYTES>>>(xh, w13h, nullptr);

    dim3 g2(R_NUM / BM, H_DIM / BN, E_NUM);    // 32 x 8 x 8
    k_gemm<2><<<g2, 256, SMEM_BYTES>>>(nullptr, w2h, out);
}

// round 14
// speedup vs baseline: 3.8729x; 1.0042x over previous
#include <cuda_runtime.h>
#include <math.h>
#include <stdint.h>

// Problem constants
#define T_TOK 2048
#define H_DIM 2048
#define E_NUM 8
#define I_DIM 5632
#define N2I   (2 * I_DIM)
#define TOPK  2
#define R_NUM (T_TOK * TOPK)

// Tiling: CTA 128x256x32 (fp16), 8 warps, warp tile 64x64
#define BM 128
#define BN 256
#define BK 32
#define STAGES 4
#define A_BYTES (BM * BK * 2)              // 8192
#define B_BYTES (BN * BK * 2)              // 16384
#define STAGE_BYTES (A_BYTES + B_BYTES)    // 24576
#define SMEM_BYTES (STAGES * STAGE_BYTES)  // 98304

// ---------------- device scratch ----------------
#define W13H_U32 (E_NUM * N2I * H_DIM / 2)
#define W2H_U32  (E_NUM * H_DIM * I_DIM / 2)
#define XH_U32   (T_TOK * H_DIM / 2)
__device__ uint32_t g_w13h[W13H_U32];          // fp16 weights (~369 MB)
__device__ uint32_t g_w2h[W2H_U32];            // (~185 MB)
__device__ uint32_t g_xh[XH_U32];              // fp16 x (8 MB)
__device__ uint32_t g_h2[(size_t)R_NUM * (I_DIM / 2)];  // fp16 h (~46 MB)
__device__ int   g_row_token[R_NUM];
__device__ float g_row_gate[R_NUM];
__device__ int   g_counts[E_NUM];
__device__ int   g_offsets[E_NUM];
__device__ int   g_tok_exp[R_NUM];
__device__ float g_tok_gate[R_NUM];

// ---------------- helpers ----------------
__device__ __forceinline__ uint32_t smem_u32(const void* p) {
    uint32_t a;
    asm("{ .reg .u64 t; cvta.to.shared.u64 t, %1; cvt.u32.u64 %0, t; }" : "=r"(a) : "l"(p));
    return a;
}
__device__ __forceinline__ uint32_t pack2(float lo, float hi) {
    uint32_t r;
    asm("cvt.rn.f16x2.f32 %0, %1, %2;" : "=r"(r) : "f"(hi), "f"(lo));
    return r;
}
// SW64 swizzle on byte offsets (rows of 64B, 16B chunk permutation)
__device__ __forceinline__ uint32_t swz64(uint32_t o) { return o ^ ((o >> 3) & 0x30); }

#define CPA(d, s, z) asm volatile("cp.async.cg.shared.global [%0], [%1], 16, %2;" :: "r"(d), "l"(s), "r"(z))
#define CPC() asm volatile("cp.async.commit_group;" ::: "memory")

#define LDSM4(r, a)                                                              \
    asm volatile("ldmatrix.sync.aligned.m8n8.x4.shared.b16 {%0,%1,%2,%3}, [%4];" \
                 : "=r"((r)[0]), "=r"((r)[1]), "=r"((r)[2]), "=r"((r)[3]) : "r"(a))

#define MMA_F16(ac, A, b0, b1)                                                   \
    asm volatile(                                                                \
        "mma.sync.aligned.m16n8k16.row.col.f32.f16.f16.f32 "                     \
        "{%0,%1,%2,%3},{%4,%5,%6,%7},{%8,%9},{%0,%1,%2,%3};"                     \
        : "+f"((ac)[0]), "+f"((ac)[1]), "+f"((ac)[2]), "+f"((ac)[3])             \
        : "r"((A)[0]), "r"((A)[1]), "r"((A)[2]), "r"((A)[3]), "r"(b0), "r"(b1))

// ---------------- routing ----------------
__global__ void k_route(const float* __restrict__ logits) {
    int t = blockIdx.x * blockDim.x + threadIdx.x;
    if (t >= T_TOK) return;
    float v[E_NUM];
    float mx = -1e30f;
#pragma unroll
    for (int e = 0; e < E_NUM; e++) { v[e] = logits[t * E_NUM + e]; mx = fmaxf(mx, v[e]); }
#pragma unroll
    for (int e = 0; e < E_NUM; e++) v[e] = __expf(v[e] - mx);
    int e1 = 0;
#pragma unroll
    for (int e = 1; e < E_NUM; e++) if (v[e] > v[e1]) e1 = e;
    int e2 = (e1 == 0) ? 1 : 0;
#pragma unroll
    for (int e = 0; e < E_NUM; e++) if (e != e1 && v[e] > v[e2]) e2 = e;
    float p1 = v[e1], p2 = v[e2];
    float inv = 1.0f / (p1 + p2);
    g_tok_exp[2 * t] = e1;  g_tok_exp[2 * t + 1] = e2;
    g_tok_gate[2 * t] = p1 * inv; g_tok_gate[2 * t + 1] = p2 * inv;
}

// single-block fused count + prefix + scatter
__global__ __launch_bounds__(1024) void k_count_scatter() {
    __shared__ int sc[E_NUM], so[E_NUM], sf[E_NUM];
    const int tid = threadIdx.x;
    if (tid < E_NUM) { sc[tid] = 0; sf[tid] = 0; }
    __syncthreads();
    for (int i = tid; i < R_NUM; i += blockDim.x)
        atomicAdd(&sc[g_tok_exp[i]], 1);
    __syncthreads();
    if (tid == 0) {
        int acc = 0;
        for (int e = 0; e < E_NUM; e++) {
            g_counts[e] = sc[e]; g_offsets[e] = acc; so[e] = acc; acc += sc[e];
        }
    }
    __syncthreads();
    for (int i = tid; i < R_NUM; i += blockDim.x) {
        const int e = g_tok_exp[i];
        const int pos = so[e] + atomicAdd(&sf[e], 1);
        g_row_token[pos] = i >> 1;
        g_row_gate[pos] = g_tok_gate[i];
    }
}

// ---------------- f32 -> f16 converts ----------------
// x and w13 in one kernel (keeps gemm1 at profiled launch slot; saturates BW)
__global__ __launch_bounds__(256) void k_cvt_xw13(const float4* __restrict__ sx,
                                                  uint2* __restrict__ dx, int nx,
                                                  const float4* __restrict__ sw,
                                                  uint2* __restrict__ dw, int nw) {
    int i = blockIdx.x * blockDim.x + threadIdx.x;
    if (i < nx) {
        float4 v = sx[i];
        uint2 o; o.x = pack2(v.x, v.y); o.y = pack2(v.z, v.w);
        dx[i] = o;
    } else {
        int j = i - nx;
        if (j < nw) {
            float4 v = sw[j];
            uint2 o; o.x = pack2(v.x, v.y); o.y = pack2(v.z, v.w);
            dw[j] = o;
        }
    }
}

__global__ __launch_bounds__(256) void k_cvt(const float4* __restrict__ s,
                                             uint2* __restrict__ d, int n4) {
    int i = blockIdx.x * blockDim.x + threadIdx.x;
    if (i >= n4) return;
    float4 v = s[i];
    uint2 o; o.x = pack2(v.x, v.y); o.y = pack2(v.z, v.w);
    d[i] = o;
}

// ---------------- fused GEMM (G=1: x@w13^T + silu*u -> g_h2 ; G=2: h@w2^T -> out) ----------------
template <int G>
__global__ __launch_bounds__(256, 1) void k_gemm(const uint32_t* __restrict__ Ah,
                                                 const uint32_t* __restrict__ Bh,
                                                 float* __restrict__ out) {
    const int e = blockIdx.z;
    const int cnt = g_counts[e];
    const int rowt = blockIdx.x * BM;
    if (rowt >= cnt) return;
    const int base = g_offsets[e];
    const int i0 = blockIdx.y * 128;   // G==1
    const int n0 = blockIdx.y * BN;    // G==2

    extern __shared__ char smem[];
    const uint32_t sb = smem_u32(smem);
    const int tid = threadIdx.x;
    const int lane = tid & 31, wid = tid >> 5;
    const int lr = lane >> 2, cg = lane & 3;
    const int wm = wid >> 2, wn = wid & 3;

    // ---- cp.async producer setup ----
    const int rA = tid >> 1;
    const int ch0 = (tid & 1) * 2;
    const uint32_t aDst0 = swz64(rA * 64 + ch0 * 16);
    const uint32_t aDst1 = swz64(rA * 64 + (ch0 + 1) * 16);
    const uint32_t* aSrc;
    uint32_t aSz = 16;
    if (G == 1) {
        const int r = rowt + rA;
        const bool av = r < cnt;
        aSz = av ? 16u : 0u;
        const int tok = av ? g_row_token[base + r] : 0;
        aSrc = Ah + (size_t)tok * (H_DIM / 2) + ch0 * 4;
    } else {
        const int r = min(rowt + rA, cnt - 1);
        aSrc = g_h2 + (size_t)(base + r) * (I_DIM / 2) + ch0 * 4;
    }
    uint32_t bDst[4];
#pragma unroll
    for (int j = 0; j < 4; j++) bDst[j] = swz64(tid * 64 + j * 16);
    const uint32_t* bSrc;
    if (G == 1) {
        const int gt = tid >> 3;   // even: gate, odd: up
        const int wr = i0 + (gt >> 1) * 8 + (tid & 7) + (gt & 1) * I_DIM;
        bSrc = Bh + (size_t)e * N2I * (H_DIM / 2) + (size_t)wr * (H_DIM / 2);
    } else {
        bSrc = Bh + (size_t)e * H_DIM * (I_DIM / 2) + (size_t)(n0 + tid) * (I_DIM / 2);
    }

    // ---- ldmatrix fragment addresses ----
    const int fr = (lane & 7) + ((lane >> 3) & 1) * 8;
    const int fc = lane >> 4;
    uint32_t aoff[4], boff[4];
#pragma unroll
    for (int mt = 0; mt < 4; mt++)
        aoff[mt] = swz64((uint32_t)((wm * 64 + mt * 16 + fr) * 64 + fc * 16));
#pragma unroll
    for (int g = 0; g < 4; g++)
        boff[g] = swz64((uint32_t)((wn * 64 + g * 16 + fr) * 64 + fc * 16));

    float acc[4][8][4];
#pragma unroll
    for (int mt = 0; mt < 4; mt++)
#pragma unroll
        for (int nt = 0; nt < 8; nt++)
#pragma unroll
            for (int c = 0; c < 4; c++) acc[mt][nt][c] = 0.f;

    const int NK = (G == 1 ? H_DIM : I_DIM) / BK;

#define ISSUE(s_, it_)                                                           \
    do {                                                                         \
        const uint32_t sbase = sb + (s_) * STAGE_BYTES;                          \
        const uint32_t* as = aSrc + (it_) * (BK / 2);                            \
        CPA(sbase + aDst0, as, aSz);                                             \
        CPA(sbase + aDst1, as + 4, aSz);                                         \
        const uint32_t* bs = bSrc + (it_) * (BK / 2);                            \
        const uint32_t bb = sbase + A_BYTES;                                     \
        CPA(bb + bDst[0], bs, 16);                                               \
        CPA(bb + bDst[1], bs + 4, 16);                                           \
        CPA(bb + bDst[2], bs + 8, 16);                                           \
        CPA(bb + bDst[3], bs + 12, 16);                                          \
    } while (0)

    // prologue: fill stages 0..STAGES-2
#pragma unroll
    for (int s = 0; s < STAGES - 1; s++) {
        if (s < NK) ISSUE(s, s);
        CPC();
    }

    for (int it = 0; it < NK; it++) {
        asm volatile("cp.async.wait_group %0;" :: "n"(STAGES - 2) : "memory");
        __syncthreads();
        const uint32_t aB = sb + (it % STAGES) * STAGE_BYTES;
        const uint32_t bB = aB + A_BYTES;
#pragma unroll
        for (int kk = 0; kk < 2; kk++) {
            uint32_t A4[4][4], B4[4][4];
#pragma unroll
            for (int mt = 0; mt < 4; mt++) LDSM4(A4[mt], aB + (aoff[mt] ^ (kk * 32)));
#pragma unroll
            for (int g = 0; g < 4; g++) LDSM4(B4[g], bB + (boff[g] ^ (kk * 32)));
#pragma unroll
            for (int mt = 0; mt < 4; mt++)
#pragma unroll
                for (int g = 0; g < 4; g++) {
                    MMA_F16(acc[mt][2 * g],     A4[mt], B4[g][0], B4[g][2]);
                    MMA_F16(acc[mt][2 * g + 1], A4[mt], B4[g][1], B4[g][3]);
                }
        }
        if (it + STAGES - 1 < NK) ISSUE((it + STAGES - 1) % STAGES, it + STAGES - 1);
        CPC();
    }
#undef ISSUE

    // ---- epilogues ----
    if (G == 1) {
#pragma unroll
        for (int mt = 0; mt < 4; mt++) {
#pragma unroll
            for (int rr = 0; rr < 2; rr++) {
                const int r = rowt + wm * 64 + mt * 16 + rr * 8 + lr;
                if (r < cnt) {
                    uint32_t* hrow = g_h2 + (size_t)(base + r) * (I_DIM / 2) + i0 / 2;
#pragma unroll
                    for (int q2 = 0; q2 < 4; q2++) {
                        const float g0 = acc[mt][2 * q2][rr * 2 + 0];
                        const float g1 = acc[mt][2 * q2][rr * 2 + 1];
                        const float u0 = acc[mt][2 * q2 + 1][rr * 2 + 0];
                        const float u1 = acc[mt][2 * q2 + 1][rr * 2 + 1];
                        const float h0 = (g0 / (1.f + __expf(-g0))) * u0;
                        const float h1 = (g1 / (1.f + __expf(-g1))) * u1;
                        hrow[(4 * wn + q2) * 4 + cg] = pack2(h0, h1);
                    }
                }
            }
        }
    } else {
#pragma unroll
        for (int mt = 0; mt < 4; mt++) {
#pragma unroll
            for (int rr = 0; rr < 2; rr++) {
                const int r = rowt + wm * 64 + mt * 16 + rr * 8 + lr;
                if (r < cnt) {
                    const int token = g_row_token[base + r];
                    const float gate = g_row_gate[base + r];
                    float* po = out + (size_t)token * H_DIM + n0 + wn * 64;
#pragma unroll
                    for (int nt = 0; nt < 8; nt++) {
                        const int col = nt * 8 + cg * 2;
                        atomicAdd(po + col,     gate * acc[mt][nt][rr * 2 + 0]);
                        atomicAdd(po + col + 1, gate * acc[mt][nt][rr * 2 + 1]);
                    }
                }
            }
        }
    }
}

// ---------------- launch ----------------
extern "C" void kernel_launch(void* const* d_in, const int* in_sizes, int n_in,
                              void* d_out, int out_size) {
    const float* x      = (const float*)d_in[0];
    const float* logits = (const float*)d_in[1];
    const float* w13    = (const float*)d_in[2];
    const float* w2     = (const float*)d_in[3];
    float* out = (float*)d_out;
    (void)in_sizes; (void)n_in;

    // one-time resources (host-side only; no device memory)
    static cudaStream_t s_side = nullptr;
    static cudaEvent_t s_fork = nullptr, s_join = nullptr;
    if (s_side == nullptr) {
        cudaStreamCreateWithFlags(&s_side, cudaStreamNonBlocking);
        cudaEventCreateWithFlags(&s_fork, cudaEventDisableTiming);
        cudaEventCreateWithFlags(&s_join, cudaEventDisableTiming);
    }
    cudaFuncSetAttribute(k_gemm<1>, cudaFuncAttributeMaxDynamicSharedMemorySize, SMEM_BYTES);
    cudaFuncSetAttribute(k_gemm<2>, cudaFuncAttributeMaxDynamicSharedMemorySize, SMEM_BYTES);

    uint32_t* w13h; cudaGetSymbolAddress((void**)&w13h, g_w13h);
    uint32_t* w2h;  cudaGetSymbolAddress((void**)&w2h,  g_w2h);
    uint32_t* xh;   cudaGetSymbolAddress((void**)&xh,   g_xh);
    const int n4_w13 = W13H_U32 / 2;      // 46,137,344
    const int n4_w2  = W2H_U32 / 2;       // 23,068,672
    const int n4_x   = XH_U32 / 2;        // 1,048,576

    // fork point for the side stream (w2 cvt depends only on input w2)
    cudaEventRecord(s_fork, 0);

    // main stream: memset(1) route(2) count_scatter(3) cvt_xw13(4) gemm1(5)...
    cudaMemsetAsync(out, 0, (size_t)out_size * sizeof(float));
    k_route<<<T_TOK / 256, 256>>>(logits);
    k_count_scatter<<<1, 1024>>>();
    {
        const int nt = n4_x + n4_w13;
        k_cvt_xw13<<<(nt + 255) / 256, 256>>>((const float4*)x, (uint2*)xh, n4_x,
                                              (const float4*)w13, (uint2*)w13h, n4_w13);
    }
    dim3 g1(R_NUM / BM, I_DIM / 128, E_NUM);   // 32 x 44 x 8 (row CTAs early-exit)
    k_gemm<1><<<g1, 256, SMEM_BYTES>>>(xh, w13h, nullptr);

    // side stream: w2 cvt runs concurrently with gemm1
    cudaStreamWaitEvent(s_side, s_fork, 0);
    k_cvt<<<(n4_w2 + 255) / 256, 256, 0, s_side>>>((const float4*)w2, (uint2*)w2h, n4_w2);
    cudaEventRecord(s_join, s_side);

    // gemm2 waits for both gemm1 (stream order) and w2 cvt (event)
    cudaStreamWaitEvent(0, s_join, 0);
    dim3 g2(R_NUM / BM, H_DIM / BN, E_NUM);    // 32 x 8 x 8
    k_gemm<2><<<g2, 256, SMEM_BYTES>>>(nullptr, w2h, out);
}

// round 15
// speedup vs baseline: 5.2434x; 1.3538x over previous
#include <cuda_runtime.h>
#include <math.h>
#include <stdint.h>

// Problem constants
#define T_TOK 2048
#define H_DIM 2048
#define E_NUM 8
#define I_DIM 5632
#define N2I   (2 * I_DIM)
#define TOPK  2
#define R_NUM (T_TOK * TOPK)

// Tiling: CTA 128x256x32 (fp16), 16 warps (4x4), warp tile 32x64
#define BM 128
#define BN 256
#define BK 32
#define NTHR 512
#define STAGES 4
#define A_BYTES (BM * BK * 2)              // 8192
#define B_BYTES (BN * BK * 2)              // 16384
#define STAGE_BYTES (A_BYTES + B_BYTES)    // 24576
#define SMEM_BYTES (STAGES * STAGE_BYTES)  // 98304

// ---------------- device scratch ----------------
#define W13H_U32 (E_NUM * N2I * H_DIM / 2)
#define W2H_U32  (E_NUM * H_DIM * I_DIM / 2)
#define XH_U32   (T_TOK * H_DIM / 2)
__device__ uint32_t g_w13h[W13H_U32];          // fp16 weights (~369 MB)
__device__ uint32_t g_w2h[W2H_U32];            // (~185 MB)
__device__ uint32_t g_xh[XH_U32];              // fp16 x (8 MB)
__device__ uint32_t g_h2[(size_t)R_NUM * (I_DIM / 2)];  // fp16 h (~46 MB)
__device__ int   g_row_token[R_NUM];
__device__ float g_row_gate[R_NUM];
__device__ int   g_counts[E_NUM];
__device__ int   g_offsets[E_NUM];
__device__ int   g_tok_exp[R_NUM];
__device__ float g_tok_gate[R_NUM];

// ---------------- helpers ----------------
__device__ __forceinline__ uint32_t smem_u32(const void* p) {
    uint32_t a;
    asm("{ .reg .u64 t; cvta.to.shared.u64 t, %1; cvt.u32.u64 %0, t; }" : "=r"(a) : "l"(p));
    return a;
}
__device__ __forceinline__ uint32_t pack2(float lo, float hi) {
    uint32_t r;
    asm("cvt.rn.f16x2.f32 %0, %1, %2;" : "=r"(r) : "f"(hi), "f"(lo));
    return r;
}
__device__ __forceinline__ uint32_t swz64(uint32_t o) { return o ^ ((o >> 3) & 0x30); }

#define CPA(d, s, z) asm volatile("cp.async.cg.shared.global [%0], [%1], 16, %2;" :: "r"(d), "l"(s), "r"(z))
#define CPC() asm volatile("cp.async.commit_group;" ::: "memory")

#define LDSM4(r, a)                                                              \
    asm volatile("ldmatrix.sync.aligned.m8n8.x4.shared.b16 {%0,%1,%2,%3}, [%4];" \
                 : "=r"((r)[0]), "=r"((r)[1]), "=r"((r)[2]), "=r"((r)[3]) : "r"(a))

#define MMA_F16(ac, A, b0, b1)                                                   \
    asm volatile(                                                                \
        "mma.sync.aligned.m16n8k16.row.col.f32.f16.f16.f32 "                     \
        "{%0,%1,%2,%3},{%4,%5,%6,%7},{%8,%9},{%0,%1,%2,%3};"                     \
        : "+f"((ac)[0]), "+f"((ac)[1]), "+f"((ac)[2]), "+f"((ac)[3])             \
        : "r"((A)[0]), "r"((A)[1]), "r"((A)[2]), "r"((A)[3]), "r"(b0), "r"(b1))

// ---------------- routing ----------------
__global__ void k_route(const float* __restrict__ logits) {
    int t = blockIdx.x * blockDim.x + threadIdx.x;
    if (t >= T_TOK) return;
    float v[E_NUM];
    float mx = -1e30f;
#pragma unroll
    for (int e = 0; e < E_NUM; e++) { v[e] = logits[t * E_NUM + e]; mx = fmaxf(mx, v[e]); }
#pragma unroll
    for (int e = 0; e < E_NUM; e++) v[e] = __expf(v[e] - mx);
    int e1 = 0;
#pragma unroll
    for (int e = 1; e < E_NUM; e++) if (v[e] > v[e1]) e1 = e;
    int e2 = (e1 == 0) ? 1 : 0;
#pragma unroll
    for (int e = 0; e < E_NUM; e++) if (e != e1 && v[e] > v[e2]) e2 = e;
    float p1 = v[e1], p2 = v[e2];
    float inv = 1.0f / (p1 + p2);
    g_tok_exp[2 * t] = e1;  g_tok_exp[2 * t + 1] = e2;
    g_tok_gate[2 * t] = p1 * inv; g_tok_gate[2 * t + 1] = p2 * inv;
}

// single-block fused count + prefix + scatter
__global__ __launch_bounds__(1024) void k_count_scatter() {
    __shared__ int sc[E_NUM], so[E_NUM], sf[E_NUM];
    const int tid = threadIdx.x;
    if (tid < E_NUM) { sc[tid] = 0; sf[tid] = 0; }
    __syncthreads();
    for (int i = tid; i < R_NUM; i += blockDim.x)
        atomicAdd(&sc[g_tok_exp[i]], 1);
    __syncthreads();
    if (tid == 0) {
        int acc = 0;
        for (int e = 0; e < E_NUM; e++) {
            g_counts[e] = sc[e]; g_offsets[e] = acc; so[e] = acc; acc += sc[e];
        }
    }
    __syncthreads();
    for (int i = tid; i < R_NUM; i += blockDim.x) {
        const int e = g_tok_exp[i];
        const int pos = so[e] + atomicAdd(&sf[e], 1);
        g_row_token[pos] = i >> 1;
        g_row_gate[pos] = g_tok_gate[i];
    }
}

// ---------------- f32 -> f16 converts ----------------
__global__ __launch_bounds__(256) void k_cvt_xw13(const float4* __restrict__ sx,
                                                  uint2* __restrict__ dx, int nx,
                                                  const float4* __restrict__ sw,
                                                  uint2* __restrict__ dw, int nw) {
    int i = blockIdx.x * blockDim.x + threadIdx.x;
    if (i < nx) {
        float4 v = sx[i];
        uint2 o; o.x = pack2(v.x, v.y); o.y = pack2(v.z, v.w);
        dx[i] = o;
    } else {
        int j = i - nx;
        if (j < nw) {
            float4 v = sw[j];
            uint2 o; o.x = pack2(v.x, v.y); o.y = pack2(v.z, v.w);
            dw[j] = o;
        }
    }
}

__global__ __launch_bounds__(256) void k_cvt(const float4* __restrict__ s,
                                             uint2* __restrict__ d, int n4) {
    int i = blockIdx.x * blockDim.x + threadIdx.x;
    if (i >= n4) return;
    float4 v = s[i];
    uint2 o; o.x = pack2(v.x, v.y); o.y = pack2(v.z, v.w);
    d[i] = o;
}

// ---------------- fused GEMM (G=1: x@w13^T + silu*u -> g_h2 ; G=2: h@w2^T -> out) ----------------
template <int G>
__global__ __launch_bounds__(NTHR, 1) void k_gemm(const uint32_t* __restrict__ Ah,
                                                  const uint32_t* __restrict__ Bh,
                                                  float* __restrict__ out) {
    const int e = blockIdx.z;
    const int cnt = g_counts[e];
    const int rowt = blockIdx.x * BM;
    if (rowt >= cnt) return;
    const int base = g_offsets[e];
    const int i0 = blockIdx.y * 128;   // G==1
    const int n0 = blockIdx.y * BN;    // G==2

    extern __shared__ char smem[];
    const uint32_t sb = smem_u32(smem);
    const int tid = threadIdx.x;
    const int lane = tid & 31, wid = tid >> 5;
    const int lr = lane >> 2, cg = lane & 3;
    const int wm = wid >> 2;    // 0..3 : 32-row band
    const int wn = wid & 3;     // 0..3 : 64-col slice

    // ---- cp.async producer setup ----
    // A: thread t loads 16B (1 chunk): row = t>>2, chunk = t&3
    const int rA = tid >> 2;
    const int chA = tid & 3;
    const uint32_t aDst = swz64(rA * 64 + chA * 16);
    const uint32_t* aSrc;
    uint32_t aSz = 16;
    if (G == 1) {
        const int r = rowt + rA;
        const bool av = r < cnt;
        aSz = av ? 16u : 0u;
        const int tok = av ? g_row_token[base + r] : 0;
        aSrc = Ah + (size_t)tok * (H_DIM / 2) + chA * 4;
    } else {
        const int r = min(rowt + rA, cnt - 1);
        aSrc = g_h2 + (size_t)(base + r) * (I_DIM / 2) + chA * 4;
    }
    // B: thread t loads 32B (2 chunks): row = t>>1, chunks (t&1)*2, +1
    const int rB = tid >> 1;
    const int chB = (tid & 1) * 2;
    const uint32_t bDst0 = swz64(rB * 64 + chB * 16);
    const uint32_t bDst1 = swz64(rB * 64 + (chB + 1) * 16);
    const uint32_t* bSrc;
    if (G == 1) {
        const int gt = rB >> 3;   // even: gate, odd: up
        const int wr = i0 + (gt >> 1) * 8 + (rB & 7) + (gt & 1) * I_DIM;
        bSrc = Bh + (size_t)e * N2I * (H_DIM / 2) + (size_t)wr * (H_DIM / 2) + chB * 4;
    } else {
        bSrc = Bh + (size_t)e * H_DIM * (I_DIM / 2) + (size_t)(n0 + rB) * (I_DIM / 2) + chB * 4;
    }

    // ---- ldmatrix fragment addresses ----
    const int fr = (lane & 7) + ((lane >> 3) & 1) * 8;
    const int fc = lane >> 4;
    uint32_t aoff[2], boff[4];
#pragma unroll
    for (int mt = 0; mt < 2; mt++)
        aoff[mt] = swz64((uint32_t)((wm * 32 + mt * 16 + fr) * 64 + fc * 16));
#pragma unroll
    for (int g = 0; g < 4; g++)
        boff[g] = swz64((uint32_t)((wn * 64 + g * 16 + fr) * 64 + fc * 16));

    float acc[2][8][4];
#pragma unroll
    for (int mt = 0; mt < 2; mt++)
#pragma unroll
        for (int nt = 0; nt < 8; nt++)
#pragma unroll
            for (int c = 0; c < 4; c++) acc[mt][nt][c] = 0.f;

    const int NK = (G == 1 ? H_DIM : I_DIM) / BK;

#define ISSUE(s_, it_)                                                           \
    do {                                                                         \
        const uint32_t sbase = sb + (s_) * STAGE_BYTES;                          \
        CPA(sbase + aDst, aSrc + (it_) * (BK / 2), aSz);                         \
        const uint32_t* bs = bSrc + (it_) * (BK / 2);                            \
        const uint32_t bb = sbase + A_BYTES;                                     \
        CPA(bb + bDst0, bs, 16);                                                 \
        CPA(bb + bDst1, bs + 4, 16);                                             \
    } while (0)

    // prologue: fill stages 0..STAGES-2
#pragma unroll
    for (int s = 0; s < STAGES - 1; s++) {
        if (s < NK) ISSUE(s, s);
        CPC();
    }

    for (int it = 0; it < NK; it++) {
        asm volatile("cp.async.wait_group %0;" :: "n"(STAGES - 2) : "memory");
        __syncthreads();
        const uint32_t aB = sb + (it % STAGES) * STAGE_BYTES;
        const uint32_t bB = aB + A_BYTES;
#pragma unroll
        for (int kk = 0; kk < 2; kk++) {
            uint32_t A4[2][4], B4[4][4];
#pragma unroll
            for (int mt = 0; mt < 2; mt++) LDSM4(A4[mt], aB + (aoff[mt] ^ (kk * 32)));
#pragma unroll
            for (int g = 0; g < 4; g++) LDSM4(B4[g], bB + (boff[g] ^ (kk * 32)));
#pragma unroll
            for (int mt = 0; mt < 2; mt++)
#pragma unroll
                for (int g = 0; g < 4; g++) {
                    MMA_F16(acc[mt][2 * g],     A4[mt], B4[g][0], B4[g][2]);
                    MMA_F16(acc[mt][2 * g + 1], A4[mt], B4[g][1], B4[g][3]);
                }
        }
        if (it + STAGES - 1 < NK) ISSUE((it + STAGES - 1) % STAGES, it + STAGES - 1);
        CPC();
    }
#undef ISSUE

    // ---- epilogues ----
    if (G == 1) {
#pragma unroll
        for (int mt = 0; mt < 2; mt++) {
#pragma unroll
            for (int rr = 0; rr < 2; rr++) {
                const int r = rowt + wm * 32 + mt * 16 + rr * 8 + lr;
                if (r < cnt) {
                    uint32_t* hrow = g_h2 + (size_t)(base + r) * (I_DIM / 2) + i0 / 2;
#pragma unroll
                    for (int q2 = 0; q2 < 4; q2++) {
                        const float g0 = acc[mt][2 * q2][rr * 2 + 0];
                        const float g1 = acc[mt][2 * q2][rr * 2 + 1];
                        const float u0 = acc[mt][2 * q2 + 1][rr * 2 + 0];
                        const float u1 = acc[mt][2 * q2 + 1][rr * 2 + 1];
                        const float h0 = (g0 / (1.f + __expf(-g0))) * u0;
                        const float h1 = (g1 / (1.f + __expf(-g1))) * u1;
                        hrow[(4 * wn + q2) * 4 + cg] = pack2(h0, h1);
                    }
                }
            }
        }
    } else {
#pragma unroll
        for (int mt = 0; mt < 2; mt++) {
#pragma unroll
            for (int rr = 0; rr < 2; rr++) {
                const int r = rowt + wm * 32 + mt * 16 + rr * 8 + lr;
                if (r < cnt) {
                    const int token = g_row_token[base + r];
                    const float gate = g_row_gate[base + r];
                    float* po = out + (size_t)token * H_DIM + n0 + wn * 64;
#pragma unroll
                    for (int nt = 0; nt < 8; nt++) {
                        const int col = nt * 8 + cg * 2;
                        atomicAdd(po + col,     gate * acc[mt][nt][rr * 2 + 0]);
                        atomicAdd(po + col + 1, gate * acc[mt][nt][rr * 2 + 1]);
                    }
                }
            }
        }
    }
}

// ---------------- launch ----------------
extern "C" void kernel_launch(void* const* d_in, const int* in_sizes, int n_in,
                              void* d_out, int out_size) {
    const float* x      = (const float*)d_in[0];
    const float* logits = (const float*)d_in[1];
    const float* w13    = (const float*)d_in[2];
    const float* w2     = (const float*)d_in[3];
    float* out = (float*)d_out;
    (void)in_sizes; (void)n_in;

    // one-time resources (host-side only; no device memory)
    static cudaStream_t s_side = nullptr;
    static cudaEvent_t s_fork = nullptr, s_join = nullptr;
    if (s_side == nullptr) {
        cudaStreamCreateWithFlags(&s_side, cudaStreamNonBlocking);
        cudaEventCreateWithFlags(&s_fork, cudaEventDisableTiming);
        cudaEventCreateWithFlags(&s_join, cudaEventDisableTiming);
    }
    cudaFuncSetAttribute(k_gemm<1>, cudaFuncAttributeMaxDynamicSharedMemorySize, SMEM_BYTES);
    cudaFuncSetAttribute(k_gemm<2>, cudaFuncAttributeMaxDynamicSharedMemorySize, SMEM_BYTES);

    uint32_t* w13h; cudaGetSymbolAddress((void**)&w13h, g_w13h);
    uint32_t* w2h;  cudaGetSymbolAddress((void**)&w2h,  g_w2h);
    uint32_t* xh;   cudaGetSymbolAddress((void**)&xh,   g_xh);
    const int n4_w13 = W13H_U32 / 2;
    const int n4_w2  = W2H_U32 / 2;
    const int n4_x   = XH_U32 / 2;

    cudaEventRecord(s_fork, 0);

    cudaMemsetAsync(out, 0, (size_t)out_size * sizeof(float));
    k_route<<<T_TOK / 256, 256>>>(logits);
    k_count_scatter<<<1, 1024>>>();
    {
        const int nt = n4_x + n4_w13;
        k_cvt_xw13<<<(nt + 255) / 256, 256>>>((const float4*)x, (uint2*)xh, n4_x,
                                              (const float4*)w13, (uint2*)w13h, n4_w13);
    }
    dim3 g1(R_NUM / BM, I_DIM / 128, E_NUM);   // 32 x 44 x 8 (row CTAs early-exit)
    k_gemm<1><<<g1, NTHR, SMEM_BYTES>>>(xh, w13h, nullptr);

    // side stream: w2 cvt runs concurrently with gemm1
    cudaStreamWaitEvent(s_side, s_fork, 0);
    k_cvt<<<(n4_w2 + 255) / 256, 256, 0, s_side>>>((const float4*)w2, (uint2*)w2h, n4_w2);
    cudaEventRecord(s_join, s_side);

    cudaStreamWaitEvent(0, s_join, 0);
    dim3 g2(R_NUM / BM, H_DIM / BN, E_NUM);    // 32 x 8 x 8
    k_gemm<2><<<g2, NTHR, SMEM_BYTES>>>(nullptr, w2h, out);
}